// round 1
// baseline (speedup 1.0000x reference)
#include <cuda_runtime.h>
#include <cuda_bf16.h>
#include <math.h>

// Problem constants
#define B_SZ   4
#define T_SEQ  2048
#define DM     1024
#define NH     16
#define DH     64
#define WIN    256
#define M_ROWS (B_SZ * T_SEQ)        // 8192
#define N_QKV  (3 * DM)              // 3072

// Scratch (device globals — allocation-free per harness rules)
__device__ float g_qkv[M_ROWS * (size_t)N_QKV];   // [8192, 3072]
__device__ float g_att[M_ROWS * (size_t)DM];      // [8192, 1024]

// ---------------------------------------------------------------------------
// SGEMM: C[M,N] = A[M,K] @ B[K,N], all row-major. 128x128 block, BK=8,
// 256 threads, 8x8 per-thread register tile. M,N,K multiples of 128/128/8.
// ---------------------------------------------------------------------------
__global__ __launch_bounds__(256, 2)
void sgemm_kernel(const float* __restrict__ A, const float* __restrict__ B,
                  float* __restrict__ C, int M, int N, int K) {
    __shared__ float As[8][128];   // transposed: As[k][m]
    __shared__ float Bs[8][128];

    const int tid = threadIdx.x;
    const int m0 = blockIdx.y * 128;
    const int n0 = blockIdx.x * 128;

    const int tm = (tid >> 4) << 3;   // 0..120
    const int tn = (tid & 15) << 3;

    // A load mapping: row r = tid/2, 4 cols starting at (tid&1)*4
    const int ar = tid >> 1;
    const int ak = (tid & 1) << 2;
    // B load mapping: row = tid/32, 4 cols at (tid%32)*4
    const int br = tid >> 5;
    const int bc = (tid & 31) << 2;

    float acc[8][8];
    #pragma unroll
    for (int i = 0; i < 8; i++)
        #pragma unroll
        for (int j = 0; j < 8; j++) acc[i][j] = 0.f;

    for (int kt = 0; kt < K; kt += 8) {
        // load A tile (128 x 8) transposed
        float4 va = *reinterpret_cast<const float4*>(&A[(size_t)(m0 + ar) * K + kt + ak]);
        As[ak + 0][ar] = va.x;
        As[ak + 1][ar] = va.y;
        As[ak + 2][ar] = va.z;
        As[ak + 3][ar] = va.w;
        // load B tile (8 x 128)
        float4 vb = *reinterpret_cast<const float4*>(&B[(size_t)(kt + br) * N + n0 + bc]);
        *reinterpret_cast<float4*>(&Bs[br][bc]) = vb;
        __syncthreads();

        #pragma unroll
        for (int k = 0; k < 8; k++) {
            float ra[8], rb[8];
            #pragma unroll
            for (int i = 0; i < 8; i++) ra[i] = As[k][tm + i];
            #pragma unroll
            for (int j = 0; j < 8; j++) rb[j] = Bs[k][tn + j];
            #pragma unroll
            for (int i = 0; i < 8; i++)
                #pragma unroll
                for (int j = 0; j < 8; j++)
                    acc[i][j] = fmaf(ra[i], rb[j], acc[i][j]);
        }
        __syncthreads();
    }

    #pragma unroll
    for (int i = 0; i < 8; i++) {
        float* crow = &C[(size_t)(m0 + tm + i) * N + n0 + tn];
        #pragma unroll
        for (int j = 0; j < 8; j++) crow[j] = acc[i][j];
    }
}

// ---------------------------------------------------------------------------
// Sliding-window attention. One block = (b, h, 64-query tile), 256 threads.
// Thread t handles query q = t>>2, output dims [(t&3)*16, +16).
// Iterate 5 key chunks of 64 covering [q0-256, q0+63], online softmax.
// Dynamic smem: Qs/Ks/Vs/Ps each 64x65 floats = 66,560 bytes.
// ---------------------------------------------------------------------------
__global__ __launch_bounds__(256)
void attn_kernel(const float* __restrict__ qkv, float* __restrict__ out) {
    extern __shared__ float sm[];
    float* Qs = sm;                // [64][65]
    float* Ks = Qs + 64 * 65;
    float* Vs = Ks + 64 * 65;
    float* Ps = Vs + 64 * 65;

    const int qt = blockIdx.x;
    const int h  = blockIdx.y;
    const int b  = blockIdx.z;
    const int q0 = qt * 64;
    const int tid = threadIdx.x;
    const int q   = tid >> 2;
    const int kgrp = tid & 3;
    const int d0 = kgrp * 16;

    const size_t base = (size_t)b * T_SEQ * N_QKV;
    const int hoff = h * DH;

    // load Q tile [64 x 64]
    for (int idx = tid; idx < 64 * 64; idx += 256) {
        int r = idx >> 6, c = idx & 63;
        Qs[r * 65 + c] = qkv[base + (size_t)(q0 + r) * N_QKV + hoff + c];
    }

    float acc[16];
    #pragma unroll
    for (int i = 0; i < 16; i++) acc[i] = 0.f;
    float m = -1e30f, l = 0.f;
    const int qg = q0 + q;

    for (int c = 0; c < 5; ++c) {
        const int kb = q0 - WIN + c * 64;
        __syncthreads();   // previous Ps/Vs reads done; Qs ready on first iter
        // load K,V chunk [64 x 64]
        for (int idx = tid; idx < 64 * 64; idx += 256) {
            int r = idx >> 6, d = idx & 63;
            int kg = kb + r;
            float kv = 0.f, vv = 0.f;
            if (kg >= 0) {   // kg < T guaranteed (kb+63 <= q0+63 < T)
                size_t o = base + (size_t)kg * N_QKV + hoff + d;
                kv = qkv[o + DM];
                vv = qkv[o + 2 * DM];
            }
            Ks[r * 65 + d] = kv;
            Vs[r * 65 + d] = vv;
        }
        __syncthreads();

        // scores for (q, 16 keys)
        float s[16];
        #pragma unroll
        for (int kk = 0; kk < 16; kk++) {
            const int kr = d0 + kk;   // key row in chunk (reuse kgrp*16)
            float dot = 0.f;
            #pragma unroll
            for (int d = 0; d < 64; d++)
                dot = fmaf(Qs[q * 65 + d], Ks[kr * 65 + d], dot);
            s[kk] = dot * 0.125f;     // 1/sqrt(64)
        }

        // masked chunk max
        float mx = -1e30f;
        #pragma unroll
        for (int kk = 0; kk < 16; kk++) {
            int kg = kb + d0 + kk;
            bool valid = (kg >= 0) && (kg <= qg) && (kg >= qg - WIN);
            if (!valid) s[kk] = -1e30f;
            mx = fmaxf(mx, s[kk]);
        }
        mx = fmaxf(mx, __shfl_xor_sync(0xffffffffu, mx, 1));
        mx = fmaxf(mx, __shfl_xor_sync(0xffffffffu, mx, 2));

        const float m_new = fmaxf(m, mx);
        const float scale = __expf(m - m_new);   // both -1e30 -> 1, harmless (acc=l=0)

        float psum = 0.f;
        #pragma unroll
        for (int kk = 0; kk < 16; kk++) {
            int kg = kb + d0 + kk;
            bool valid = (kg >= 0) && (kg <= qg) && (kg >= qg - WIN);
            float p = valid ? __expf(s[kk] - m_new) : 0.f;
            Ps[q * 65 + d0 + kk] = p;
            psum += p;
        }
        psum += __shfl_xor_sync(0xffffffffu, psum, 1);
        psum += __shfl_xor_sync(0xffffffffu, psum, 2);
        l = l * scale + psum;
        m = m_new;
        #pragma unroll
        for (int i = 0; i < 16; i++) acc[i] *= scale;
        __syncthreads();

        // acc += P @ V for this thread's 16 dims
        #pragma unroll 4
        for (int kr = 0; kr < 64; kr++) {
            float p = Ps[q * 65 + kr];
            #pragma unroll
            for (int i = 0; i < 16; i++)
                acc[i] = fmaf(p, Vs[kr * 65 + d0 + i], acc[i]);
        }
    }

    const float inv_l = 1.f / l;   // l >= exp(0): self key always valid
    float* orow = &out[(size_t)(b * T_SEQ + qg) * DM + hoff + d0];
    #pragma unroll
    for (int i = 0; i < 16; i++) orow[i] = acc[i] * inv_l;
}

// ---------------------------------------------------------------------------
extern "C" void kernel_launch(void* const* d_in, const int* in_sizes, int n_in,
                              void* d_out, int out_size) {
    const float* x     = (const float*)d_in[0];   // [4,2048,1024]
    const float* w_qkv = (const float*)d_in[1];   // [1024,3072]
    const float* w_out = (const float*)d_in[2];   // [1024,1024]
    float* out = (float*)d_out;                   // [4,2048,1024]

    float* qkv_buf = nullptr;
    float* att_buf = nullptr;
    cudaGetSymbolAddress((void**)&qkv_buf, g_qkv);
    cudaGetSymbolAddress((void**)&att_buf, g_att);

    const int ATTN_SMEM = 4 * 64 * 65 * (int)sizeof(float);   // 66,560 B
    cudaFuncSetAttribute(attn_kernel, cudaFuncAttributeMaxDynamicSharedMemorySize, ATTN_SMEM);

    // 1) QKV projection: [8192,1024] @ [1024,3072]
    {
        dim3 grid(N_QKV / 128, M_ROWS / 128);
        sgemm_kernel<<<grid, 256>>>(x, w_qkv, qkv_buf, M_ROWS, N_QKV, DM);
    }
    // 2) sliding-window attention
    {
        dim3 grid(T_SEQ / 64, NH, B_SZ);
        attn_kernel<<<grid, 256, ATTN_SMEM>>>(qkv_buf, att_buf);
    }
    // 3) output projection: [8192,1024] @ [1024,1024]
    {
        dim3 grid(DM / 128, M_ROWS / 128);
        sgemm_kernel<<<grid, 256>>>(att_buf, w_out, out, M_ROWS, DM, DM);
    }
}

// round 2
// speedup vs baseline: 1.4590x; 1.4590x over previous
#include <cuda_runtime.h>
#include <cuda_bf16.h>
#include <math.h>
#include <stdint.h>

// Problem constants
#define B_SZ   4
#define T_SEQ  2048
#define DM     1024
#define NH     16
#define DH     64
#define WIN    256
#define M_ROWS (B_SZ * T_SEQ)        // 8192
#define N_QKV  (3 * DM)              // 3072

// GEMM tiling
#define BM 128
#define BN 128
#define BKK 32
#define PAD 8
#define LDS_K (BKK + PAD)            // 40 bf16 elems per row

// ---------------------------------------------------------------------------
// Device scratch (allocation-free per harness rules)
// ---------------------------------------------------------------------------
__device__ __align__(16) __nv_bfloat16 g_x_hi[M_ROWS * (size_t)DM];
__device__ __align__(16) __nv_bfloat16 g_x_lo[M_ROWS * (size_t)DM];
__device__ __align__(16) __nv_bfloat16 g_wqkvT_hi[N_QKV * (size_t)DM];   // [N][K]
__device__ __align__(16) __nv_bfloat16 g_wqkvT_lo[N_QKV * (size_t)DM];
__device__ __align__(16) __nv_bfloat16 g_woutT_hi[DM * (size_t)DM];      // [N][K]
__device__ __align__(16) __nv_bfloat16 g_woutT_lo[DM * (size_t)DM];
__device__ __align__(16) float g_qkv[M_ROWS * (size_t)N_QKV];            // [8192,3072]
__device__ __align__(16) float g_att[M_ROWS * (size_t)DM];               // [8192,1024]
__device__ __align__(16) __nv_bfloat16 g_att_hi[M_ROWS * (size_t)DM];
__device__ __align__(16) __nv_bfloat16 g_att_lo[M_ROWS * (size_t)DM];

// ---------------------------------------------------------------------------
// Helpers
// ---------------------------------------------------------------------------
__device__ __forceinline__ uint32_t smem_u32(const void* p) {
    return (uint32_t)__cvta_generic_to_shared(p);
}

#define CP16(saddr, gptr) \
    asm volatile("cp.async.cg.shared.global [%0], [%1], 16;" :: "r"(saddr), "l"(gptr))
#define CP_COMMIT() asm volatile("cp.async.commit_group;")
#define CP_WAIT(n)  asm volatile("cp.async.wait_group %0;" :: "n"(n))

#define LDM4(r, addr) \
    asm volatile("ldmatrix.sync.aligned.m8n8.x4.shared.b16 {%0,%1,%2,%3}, [%4];" \
        : "=r"((r)[0]), "=r"((r)[1]), "=r"((r)[2]), "=r"((r)[3]) : "r"(addr))

#define MMA16816(d, a, b0, b1) \
    asm volatile("mma.sync.aligned.m16n8k16.row.col.f32.bf16.bf16.f32 " \
        "{%0,%1,%2,%3}, {%4,%5,%6,%7}, {%8,%9}, {%0,%1,%2,%3};" \
        : "+f"((d)[0]), "+f"((d)[1]), "+f"((d)[2]), "+f"((d)[3]) \
        : "r"((a)[0]), "r"((a)[1]), "r"((a)[2]), "r"((a)[3]), "r"(b0), "r"(b1))

__device__ __forceinline__ void split_f32(float f, __nv_bfloat16& hi, __nv_bfloat16& lo) {
    hi = __float2bfloat16_rn(f);
    lo = __float2bfloat16_rn(f - __bfloat162float(hi));
}

// ---------------------------------------------------------------------------
// Elementwise split: fp32 -> (hi, lo) bf16
// ---------------------------------------------------------------------------
__global__ void split_kernel(const float* __restrict__ src,
                             __nv_bfloat16* __restrict__ hi,
                             __nv_bfloat16* __restrict__ lo, int n4) {
    int i = blockIdx.x * blockDim.x + threadIdx.x;
    if (i >= n4) return;
    float4 f = reinterpret_cast<const float4*>(src)[i];
    __nv_bfloat16 h0, h1, h2, h3, l0, l1, l2, l3;
    split_f32(f.x, h0, l0); split_f32(f.y, h1, l1);
    split_f32(f.z, h2, l2); split_f32(f.w, h3, l3);
    __nv_bfloat162* hp = reinterpret_cast<__nv_bfloat162*>(hi) + i * 2;
    __nv_bfloat162* lp = reinterpret_cast<__nv_bfloat162*>(lo) + i * 2;
    hp[0] = __nv_bfloat162(h0, h1); hp[1] = __nv_bfloat162(h2, h3);
    lp[0] = __nv_bfloat162(l0, l1); lp[1] = __nv_bfloat162(l2, l3);
}

// ---------------------------------------------------------------------------
// Transpose + split: src [K][N] fp32 -> dst [N][K] bf16 hi/lo
// ---------------------------------------------------------------------------
__global__ void transpose_split_kernel(const float* __restrict__ src,
                                       __nv_bfloat16* __restrict__ hi,
                                       __nv_bfloat16* __restrict__ lo,
                                       int K, int N) {
    __shared__ float t[32][33];
    const int n0 = blockIdx.x * 32;
    const int k0 = blockIdx.y * 32;
    const int tx = threadIdx.x & 31;
    const int ty = threadIdx.x >> 5;     // 0..7
    #pragma unroll
    for (int i = 0; i < 32; i += 8)
        t[ty + i][tx] = src[(size_t)(k0 + ty + i) * N + n0 + tx];
    __syncthreads();
    #pragma unroll
    for (int i = 0; i < 32; i += 8) {
        float f = t[tx][ty + i];         // src[k0+tx][n0+ty+i]
        __nv_bfloat16 h, l;
        split_f32(f, h, l);
        size_t o = (size_t)(n0 + ty + i) * K + k0 + tx;
        hi[o] = h;
        lo[o] = l;
    }
}

// ---------------------------------------------------------------------------
// bf16x3 GEMM: C[M][N] fp32 = A[M][K] @ B^T where Bt is [N][K].
// A,Bt given as (hi,lo) bf16 pairs. 128x128x32 tiles, 256 threads (8 warps,
// 4(M) x 2(N)), mma.m16n8k16, cp.async double buffer.
// ---------------------------------------------------------------------------
__global__ __launch_bounds__(256, 1)
void gemm_bf16x3(const __nv_bfloat16* __restrict__ Ah, const __nv_bfloat16* __restrict__ Al,
                 const __nv_bfloat16* __restrict__ Bh, const __nv_bfloat16* __restrict__ Bl,
                 float* __restrict__ C, int M, int N, int K) {
    extern __shared__ __nv_bfloat16 sm[];
    const int SSZ = 4 * BM * LDS_K;              // elems per stage
    const int AH_B = 0;                          // byte offsets within stage
    const int AL_B = BM * LDS_K * 2;
    const int BH_B = 2 * BM * LDS_K * 2;
    const int BL_B = 3 * BM * LDS_K * 2;

    const int tid  = threadIdx.x;
    const int lane = tid & 31;
    const int warp = tid >> 5;
    const int wm   = warp & 3;                   // 0..3 (32 rows each)
    const int wn   = warp >> 2;                  // 0..1 (64 cols each)
    const int m0   = blockIdx.y * BM;
    const int n0   = blockIdx.x * BN;

    const uint32_t s0 = smem_u32(sm);
    const uint32_t s1 = smem_u32(sm + SSZ);

    // loader mapping: 64 rows per pass, 8 k-elems (16B) per thread
    const int lr = tid >> 2;                     // 0..63
    const int lk = (tid & 3) * 8;

    float acc[2][8][4];
    #pragma unroll
    for (int a = 0; a < 2; a++)
        #pragma unroll
        for (int b = 0; b < 8; b++)
            #pragma unroll
            for (int c = 0; c < 4; c++) acc[a][b][c] = 0.f;

    const int NK = K / BKK;

    // ---- stage loader ----
    auto load_stage = [&](uint32_t sbase, int kt) {
        #pragma unroll
        for (int it = 0; it < 2; ++it) {
            int row = lr + it * 64;
            uint32_t so = (uint32_t)(row * LDS_K + lk) * 2;
            size_t ga = (size_t)(m0 + row) * K + kt + lk;
            size_t gb = (size_t)(n0 + row) * K + kt + lk;
            CP16(sbase + AH_B + so, Ah + ga);
            CP16(sbase + AL_B + so, Al + ga);
            CP16(sbase + BH_B + so, Bh + gb);
            CP16(sbase + BL_B + so, Bl + gb);
        }
    };

    load_stage(s0, 0);
    CP_COMMIT();

    // ldmatrix address precompute (row/col within tile)
    const int a_row = wm * 32 + (lane & 15);
    const int a_coloff = (lane >> 4) << 3;           // 0 or 8
    const int b_row = wn * 64 + (lane & 7) + ((lane >> 4) << 3);
    const int b_koff = ((lane >> 3) & 1) << 3;       // 0 or 8

    for (int kt = 0; kt < NK; ++kt) {
        uint32_t scur = (kt & 1) ? s1 : s0;
        uint32_t snxt = (kt & 1) ? s0 : s1;
        if (kt + 1 < NK) {
            load_stage(snxt, (kt + 1) * BKK);
            CP_COMMIT();
            CP_WAIT(1);
        } else {
            CP_WAIT(0);
        }
        __syncthreads();

        #pragma unroll
        for (int ks = 0; ks < 2; ++ks) {
            uint32_t ah[2][4], al[2][4];
            #pragma unroll
            for (int mt = 0; mt < 2; ++mt) {
                uint32_t ad = scur + (uint32_t)((a_row + mt * 16) * LDS_K
                                                + ks * 16 + a_coloff) * 2;
                LDM4(ah[mt], ad + AH_B);
                LDM4(al[mt], ad + AL_B);
            }
            #pragma unroll
            for (int np = 0; np < 4; ++np) {
                uint32_t bd = scur + (uint32_t)((b_row + np * 16) * LDS_K
                                                + ks * 16 + b_koff) * 2;
                uint32_t bh[4], bl[4];
                LDM4(bh, bd + BH_B);
                LDM4(bl, bd + BL_B);
                #pragma unroll
                for (int mt = 0; mt < 2; ++mt) {
                    MMA16816(acc[mt][2 * np],     ah[mt], bh[0], bh[1]);
                    MMA16816(acc[mt][2 * np],     ah[mt], bl[0], bl[1]);
                    MMA16816(acc[mt][2 * np],     al[mt], bh[0], bh[1]);
                    MMA16816(acc[mt][2 * np + 1], ah[mt], bh[2], bh[3]);
                    MMA16816(acc[mt][2 * np + 1], ah[mt], bl[2], bl[3]);
                    MMA16816(acc[mt][2 * np + 1], al[mt], bh[2], bh[3]);
                }
            }
        }
        __syncthreads();
    }

    // ---- epilogue ----
    #pragma unroll
    for (int mt = 0; mt < 2; ++mt) {
        #pragma unroll
        for (int nt = 0; nt < 8; ++nt) {
            int row = m0 + wm * 32 + mt * 16 + (lane >> 2);
            int col = n0 + wn * 64 + nt * 8 + (lane & 3) * 2;
            float2 v0 = make_float2(acc[mt][nt][0], acc[mt][nt][1]);
            float2 v1 = make_float2(acc[mt][nt][2], acc[mt][nt][3]);
            *reinterpret_cast<float2*>(&C[(size_t)row * N + col]) = v0;
            *reinterpret_cast<float2*>(&C[(size_t)(row + 8) * N + col]) = v1;
        }
    }
}

// ---------------------------------------------------------------------------
// Sliding-window attention (fp32, unchanged from passing Round-1 kernel).
// ---------------------------------------------------------------------------
__global__ __launch_bounds__(256)
void attn_kernel(const float* __restrict__ qkv, float* __restrict__ out) {
    extern __shared__ float smf[];
    float* Qs = smf;               // [64][65]
    float* Ks = Qs + 64 * 65;
    float* Vs = Ks + 64 * 65;
    float* Ps = Vs + 64 * 65;

    const int qt = blockIdx.x;
    const int h  = blockIdx.y;
    const int b  = blockIdx.z;
    const int q0 = qt * 64;
    const int tid = threadIdx.x;
    const int q   = tid >> 2;
    const int d0 = (tid & 3) * 16;

    const size_t base = (size_t)b * T_SEQ * N_QKV;
    const int hoff = h * DH;

    for (int idx = tid; idx < 64 * 64; idx += 256) {
        int r = idx >> 6, c = idx & 63;
        Qs[r * 65 + c] = qkv[base + (size_t)(q0 + r) * N_QKV + hoff + c];
    }

    float acc[16];
    #pragma unroll
    for (int i = 0; i < 16; i++) acc[i] = 0.f;
    float m = -1e30f, l = 0.f;
    const int qg = q0 + q;

    for (int c = 0; c < 5; ++c) {
        const int kb = q0 - WIN + c * 64;
        __syncthreads();
        for (int idx = tid; idx < 64 * 64; idx += 256) {
            int r = idx >> 6, d = idx & 63;
            int kg = kb + r;
            float kv = 0.f, vv = 0.f;
            if (kg >= 0) {
                size_t o = base + (size_t)kg * N_QKV + hoff + d;
                kv = qkv[o + DM];
                vv = qkv[o + 2 * DM];
            }
            Ks[r * 65 + d] = kv;
            Vs[r * 65 + d] = vv;
        }
        __syncthreads();

        float s[16];
        #pragma unroll
        for (int kk = 0; kk < 16; kk++) {
            const int kr = d0 + kk;
            float dot = 0.f;
            #pragma unroll
            for (int d = 0; d < 64; d++)
                dot = fmaf(Qs[q * 65 + d], Ks[kr * 65 + d], dot);
            s[kk] = dot * 0.125f;
        }

        float mx = -1e30f;
        #pragma unroll
        for (int kk = 0; kk < 16; kk++) {
            int kg = kb + d0 + kk;
            bool valid = (kg >= 0) && (kg <= qg) && (kg >= qg - WIN);
            if (!valid) s[kk] = -1e30f;
            mx = fmaxf(mx, s[kk]);
        }
        mx = fmaxf(mx, __shfl_xor_sync(0xffffffffu, mx, 1));
        mx = fmaxf(mx, __shfl_xor_sync(0xffffffffu, mx, 2));

        const float m_new = fmaxf(m, mx);
        const float scale = __expf(m - m_new);

        float psum = 0.f;
        #pragma unroll
        for (int kk = 0; kk < 16; kk++) {
            int kg = kb + d0 + kk;
            bool valid = (kg >= 0) && (kg <= qg) && (kg >= qg - WIN);
            float p = valid ? __expf(s[kk] - m_new) : 0.f;
            Ps[q * 65 + d0 + kk] = p;
            psum += p;
        }
        psum += __shfl_xor_sync(0xffffffffu, psum, 1);
        psum += __shfl_xor_sync(0xffffffffu, psum, 2);
        l = l * scale + psum;
        m = m_new;
        #pragma unroll
        for (int i = 0; i < 16; i++) acc[i] *= scale;
        __syncthreads();

        #pragma unroll 4
        for (int kr = 0; kr < 64; kr++) {
            float p = Ps[q * 65 + kr];
            #pragma unroll
            for (int i = 0; i < 16; i++)
                acc[i] = fmaf(p, Vs[kr * 65 + d0 + i], acc[i]);
        }
    }

    const float inv_l = 1.f / l;
    float* orow = &out[(size_t)(b * T_SEQ + qg) * DM + hoff + d0];
    #pragma unroll
    for (int i = 0; i < 16; i++) orow[i] = acc[i] * inv_l;
}

// ---------------------------------------------------------------------------
extern "C" void kernel_launch(void* const* d_in, const int* in_sizes, int n_in,
                              void* d_out, int out_size) {
    const float* x     = (const float*)d_in[0];   // [4,2048,1024]
    const float* w_qkv = (const float*)d_in[1];   // [1024,3072]
    const float* w_out = (const float*)d_in[2];   // [1024,1024]
    float* out = (float*)d_out;                   // [4,2048,1024]

    __nv_bfloat16 *x_hi, *x_lo, *wq_hi, *wq_lo, *wo_hi, *wo_lo, *at_hi, *at_lo;
    float *qkv_buf, *att_buf;
    cudaGetSymbolAddress((void**)&x_hi,  g_x_hi);
    cudaGetSymbolAddress((void**)&x_lo,  g_x_lo);
    cudaGetSymbolAddress((void**)&wq_hi, g_wqkvT_hi);
    cudaGetSymbolAddress((void**)&wq_lo, g_wqkvT_lo);
    cudaGetSymbolAddress((void**)&wo_hi, g_woutT_hi);
    cudaGetSymbolAddress((void**)&wo_lo, g_woutT_lo);
    cudaGetSymbolAddress((void**)&at_hi, g_att_hi);
    cudaGetSymbolAddress((void**)&at_lo, g_att_lo);
    cudaGetSymbolAddress((void**)&qkv_buf, g_qkv);
    cudaGetSymbolAddress((void**)&att_buf, g_att);

    const int GEMM_SMEM = 2 * 4 * BM * LDS_K * (int)sizeof(__nv_bfloat16);  // 81920
    cudaFuncSetAttribute(gemm_bf16x3, cudaFuncAttributeMaxDynamicSharedMemorySize, GEMM_SMEM);
    const int ATTN_SMEM = 4 * 64 * 65 * (int)sizeof(float);                  // 66560
    cudaFuncSetAttribute(attn_kernel, cudaFuncAttributeMaxDynamicSharedMemorySize, ATTN_SMEM);

    // 0) precision splits / weight transposes
    {
        int n4 = M_ROWS * DM / 4;
        split_kernel<<<(n4 + 255) / 256, 256>>>(x, x_hi, x_lo, n4);
        dim3 g1(N_QKV / 32, DM / 32);
        transpose_split_kernel<<<g1, 256>>>(w_qkv, wq_hi, wq_lo, DM, N_QKV);
        dim3 g2(DM / 32, DM / 32);
        transpose_split_kernel<<<g2, 256>>>(w_out, wo_hi, wo_lo, DM, DM);
    }
    // 1) QKV projection: [8192,1024] @ [1024,3072] via bf16x3 tensor cores
    {
        dim3 grid(N_QKV / BN, M_ROWS / BM);
        gemm_bf16x3<<<grid, 256, GEMM_SMEM>>>(x_hi, x_lo, wq_hi, wq_lo,
                                              qkv_buf, M_ROWS, N_QKV, DM);
    }
    // 2) sliding-window attention
    {
        dim3 grid(T_SEQ / 64, NH, B_SZ);
        attn_kernel<<<grid, 256, ATTN_SMEM>>>(qkv_buf, att_buf);
    }
    // 3) output projection
    {
        int n4 = M_ROWS * DM / 4;
        split_kernel<<<(n4 + 255) / 256, 256>>>(att_buf, at_hi, at_lo, n4);
        dim3 grid(DM / BN, M_ROWS / BM);
        gemm_bf16x3<<<grid, 256, GEMM_SMEM>>>(at_hi, at_lo, wo_hi, wo_lo,
                                              out, M_ROWS, DM, DM);
    }
}

// round 3
// speedup vs baseline: 3.7620x; 2.5784x over previous
#include <cuda_runtime.h>
#include <cuda_bf16.h>
#include <math.h>
#include <stdint.h>

// Problem constants
#define B_SZ   4
#define T_SEQ  2048
#define DM     1024
#define NH     16
#define DH     64
#define WIN    256
#define M_ROWS (B_SZ * T_SEQ)        // 8192
#define N_QKV  (3 * DM)              // 3072

// GEMM tiling
#define BM 128
#define BN 128
#define BKK 32
#define PAD 8
#define LDS_K (BKK + PAD)            // 40 bf16 elems per row

// ---------------------------------------------------------------------------
// Device scratch (allocation-free per harness rules)
// ---------------------------------------------------------------------------
__device__ __align__(16) __nv_bfloat16 g_x_hi[M_ROWS * (size_t)DM];
__device__ __align__(16) __nv_bfloat16 g_x_lo[M_ROWS * (size_t)DM];
__device__ __align__(16) __nv_bfloat16 g_wqkvT_hi[N_QKV * (size_t)DM];   // [N][K]
__device__ __align__(16) __nv_bfloat16 g_wqkvT_lo[N_QKV * (size_t)DM];
__device__ __align__(16) __nv_bfloat16 g_woutT_hi[DM * (size_t)DM];      // [N][K]
__device__ __align__(16) __nv_bfloat16 g_woutT_lo[DM * (size_t)DM];
__device__ __align__(16) float g_qkv[M_ROWS * (size_t)N_QKV];            // [8192,3072]
__device__ __align__(16) __nv_bfloat16 g_att_hi[M_ROWS * (size_t)DM];
__device__ __align__(16) __nv_bfloat16 g_att_lo[M_ROWS * (size_t)DM];

// ---------------------------------------------------------------------------
// Helpers
// ---------------------------------------------------------------------------
__device__ __forceinline__ uint32_t smem_u32(const void* p) {
    return (uint32_t)__cvta_generic_to_shared(p);
}

#define CP16(saddr, gptr) \
    asm volatile("cp.async.cg.shared.global [%0], [%1], 16;" :: "r"(saddr), "l"(gptr))
#define CP_COMMIT() asm volatile("cp.async.commit_group;")
#define CP_WAIT(n)  asm volatile("cp.async.wait_group %0;" :: "n"(n))

#define LDM4(r, addr) \
    asm volatile("ldmatrix.sync.aligned.m8n8.x4.shared.b16 {%0,%1,%2,%3}, [%4];" \
        : "=r"((r)[0]), "=r"((r)[1]), "=r"((r)[2]), "=r"((r)[3]) : "r"(addr))

#define LDM4T(r, addr) \
    asm volatile("ldmatrix.sync.aligned.m8n8.x4.trans.shared.b16 {%0,%1,%2,%3}, [%4];" \
        : "=r"((r)[0]), "=r"((r)[1]), "=r"((r)[2]), "=r"((r)[3]) : "r"(addr))

#define MMA16816(d, a, b0, b1) \
    asm volatile("mma.sync.aligned.m16n8k16.row.col.f32.bf16.bf16.f32 " \
        "{%0,%1,%2,%3}, {%4,%5,%6,%7}, {%8,%9}, {%0,%1,%2,%3};" \
        : "+f"((d)[0]), "+f"((d)[1]), "+f"((d)[2]), "+f"((d)[3]) \
        : "r"((a)[0]), "r"((a)[1]), "r"((a)[2]), "r"((a)[3]), "r"(b0), "r"(b1))

__device__ __forceinline__ void split_f32(float f, __nv_bfloat16& hi, __nv_bfloat16& lo) {
    hi = __float2bfloat16_rn(f);
    lo = __float2bfloat16_rn(f - __bfloat162float(hi));
}

// pack 2 fp32 -> bf16x2 hi and lo words
__device__ __forceinline__ void pack2_hilo(float x, float y, uint32_t& h, uint32_t& l) {
    __nv_bfloat162 hv, lv;
    split_f32(x, hv.x, lv.x);
    split_f32(y, hv.y, lv.y);
    h = *reinterpret_cast<uint32_t*>(&hv);
    l = *reinterpret_cast<uint32_t*>(&lv);
}

// split a float4 and store 4 bf16 hi + 4 bf16 lo (two bf16x2 stores each)
__device__ __forceinline__ void split_store4(float4 f, __nv_bfloat16* hp, __nv_bfloat16* lp) {
    __nv_bfloat162 h01, l01, h23, l23;
    split_f32(f.x, h01.x, l01.x);
    split_f32(f.y, h01.y, l01.y);
    split_f32(f.z, h23.x, l23.x);
    split_f32(f.w, h23.y, l23.y);
    *reinterpret_cast<__nv_bfloat162*>(hp)     = h01;
    *reinterpret_cast<__nv_bfloat162*>(hp + 2) = h23;
    *reinterpret_cast<__nv_bfloat162*>(lp)     = l01;
    *reinterpret_cast<__nv_bfloat162*>(lp + 2) = l23;
}

// ---------------------------------------------------------------------------
// Elementwise split: fp32 -> (hi, lo) bf16
// ---------------------------------------------------------------------------
__global__ void split_kernel(const float* __restrict__ src,
                             __nv_bfloat16* __restrict__ hi,
                             __nv_bfloat16* __restrict__ lo, int n4) {
    int i = blockIdx.x * blockDim.x + threadIdx.x;
    if (i >= n4) return;
    float4 f = reinterpret_cast<const float4*>(src)[i];
    split_store4(f, hi + i * 4, lo + i * 4);
}

// ---------------------------------------------------------------------------
// Transpose + split: src [K][N] fp32 -> dst [N][K] bf16 hi/lo
// ---------------------------------------------------------------------------
__global__ void transpose_split_kernel(const float* __restrict__ src,
                                       __nv_bfloat16* __restrict__ hi,
                                       __nv_bfloat16* __restrict__ lo,
                                       int K, int N) {
    __shared__ float t[32][33];
    const int n0 = blockIdx.x * 32;
    const int k0 = blockIdx.y * 32;
    const int tx = threadIdx.x & 31;
    const int ty = threadIdx.x >> 5;     // 0..7
    #pragma unroll
    for (int i = 0; i < 32; i += 8)
        t[ty + i][tx] = src[(size_t)(k0 + ty + i) * N + n0 + tx];
    __syncthreads();
    #pragma unroll
    for (int i = 0; i < 32; i += 8) {
        float f = t[tx][ty + i];
        __nv_bfloat16 h, l;
        split_f32(f, h, l);
        size_t o = (size_t)(n0 + ty + i) * K + k0 + tx;
        hi[o] = h;
        lo[o] = l;
    }
}

// ---------------------------------------------------------------------------
// bf16x3 GEMM (unchanged from Round 2): C[M][N] fp32 = A @ B^T (Bt is [N][K])
// ---------------------------------------------------------------------------
__global__ __launch_bounds__(256, 1)
void gemm_bf16x3(const __nv_bfloat16* __restrict__ Ah, const __nv_bfloat16* __restrict__ Al,
                 const __nv_bfloat16* __restrict__ Bh, const __nv_bfloat16* __restrict__ Bl,
                 float* __restrict__ C, int M, int N, int K) {
    extern __shared__ __nv_bfloat16 sm[];
    const int SSZ = 4 * BM * LDS_K;
    const int AH_B = 0;
    const int AL_B = BM * LDS_K * 2;
    const int BH_B = 2 * BM * LDS_K * 2;
    const int BL_B = 3 * BM * LDS_K * 2;

    const int tid  = threadIdx.x;
    const int lane = tid & 31;
    const int warp = tid >> 5;
    const int wm   = warp & 3;
    const int wn   = warp >> 2;
    const int m0   = blockIdx.y * BM;
    const int n0   = blockIdx.x * BN;

    const uint32_t s0 = smem_u32(sm);
    const uint32_t s1 = smem_u32(sm + SSZ);

    const int lr = tid >> 2;
    const int lk = (tid & 3) * 8;

    float acc[2][8][4];
    #pragma unroll
    for (int a = 0; a < 2; a++)
        #pragma unroll
        for (int b = 0; b < 8; b++)
            #pragma unroll
            for (int c = 0; c < 4; c++) acc[a][b][c] = 0.f;

    const int NK = K / BKK;

    auto load_stage = [&](uint32_t sbase, int kt) {
        #pragma unroll
        for (int it = 0; it < 2; ++it) {
            int row = lr + it * 64;
            uint32_t so = (uint32_t)(row * LDS_K + lk) * 2;
            size_t ga = (size_t)(m0 + row) * K + kt + lk;
            size_t gb = (size_t)(n0 + row) * K + kt + lk;
            CP16(sbase + AH_B + so, Ah + ga);
            CP16(sbase + AL_B + so, Al + ga);
            CP16(sbase + BH_B + so, Bh + gb);
            CP16(sbase + BL_B + so, Bl + gb);
        }
    };

    load_stage(s0, 0);
    CP_COMMIT();

    const int a_row = wm * 32 + (lane & 15);
    const int a_coloff = (lane >> 4) << 3;
    const int b_row = wn * 64 + (lane & 7) + ((lane >> 4) << 3);
    const int b_koff = ((lane >> 3) & 1) << 3;

    for (int kt = 0; kt < NK; ++kt) {
        uint32_t scur = (kt & 1) ? s1 : s0;
        uint32_t snxt = (kt & 1) ? s0 : s1;
        if (kt + 1 < NK) {
            load_stage(snxt, (kt + 1) * BKK);
            CP_COMMIT();
            CP_WAIT(1);
        } else {
            CP_WAIT(0);
        }
        __syncthreads();

        #pragma unroll
        for (int ks = 0; ks < 2; ++ks) {
            uint32_t ah[2][4], al[2][4];
            #pragma unroll
            for (int mt = 0; mt < 2; ++mt) {
                uint32_t ad = scur + (uint32_t)((a_row + mt * 16) * LDS_K
                                                + ks * 16 + a_coloff) * 2;
                LDM4(ah[mt], ad + AH_B);
                LDM4(al[mt], ad + AL_B);
            }
            #pragma unroll
            for (int np = 0; np < 4; ++np) {
                uint32_t bd = scur + (uint32_t)((b_row + np * 16) * LDS_K
                                                + ks * 16 + b_koff) * 2;
                uint32_t bh[4], bl[4];
                LDM4(bh, bd + BH_B);
                LDM4(bl, bd + BL_B);
                #pragma unroll
                for (int mt = 0; mt < 2; ++mt) {
                    MMA16816(acc[mt][2 * np],     ah[mt], bh[0], bh[1]);
                    MMA16816(acc[mt][2 * np],     ah[mt], bl[0], bl[1]);
                    MMA16816(acc[mt][2 * np],     al[mt], bh[0], bh[1]);
                    MMA16816(acc[mt][2 * np + 1], ah[mt], bh[2], bh[3]);
                    MMA16816(acc[mt][2 * np + 1], ah[mt], bl[2], bl[3]);
                    MMA16816(acc[mt][2 * np + 1], al[mt], bh[2], bh[3]);
                }
            }
        }
        __syncthreads();
    }

    #pragma unroll
    for (int mt = 0; mt < 2; ++mt) {
        #pragma unroll
        for (int nt = 0; nt < 8; ++nt) {
            int row = m0 + wm * 32 + mt * 16 + (lane >> 2);
            int col = n0 + wn * 64 + nt * 8 + (lane & 3) * 2;
            float2 v0 = make_float2(acc[mt][nt][0], acc[mt][nt][1]);
            float2 v1 = make_float2(acc[mt][nt][2], acc[mt][nt][3]);
            *reinterpret_cast<float2*>(&C[(size_t)row * N + col]) = v0;
            *reinterpret_cast<float2*>(&C[(size_t)(row + 8) * N + col]) = v1;
        }
    }
}

// ---------------------------------------------------------------------------
// Tensor-core sliding-window attention (bf16x3).
// Block = (64-query tile, head, batch), 128 threads = 4 warps x 16 rows.
// S = Q K^T via mma.m16n8k16 (3-term hi/lo), online softmax in C-fragments,
// O += P V (P split in registers, V hi/lo via ldmatrix.trans, 3-term).
// Output written directly as bf16 hi/lo splits for the next GEMM.
// ---------------------------------------------------------------------------
#define AST 72   // smem row stride (64 + 8 pad), bf16 elems

__global__ __launch_bounds__(128, 4)
void attn_tc_kernel(const float* __restrict__ qkv,
                    __nv_bfloat16* __restrict__ out_hi,
                    __nv_bfloat16* __restrict__ out_lo) {
    extern __shared__ __nv_bfloat16 smb[];
    const int REG = 64 * AST;
    __nv_bfloat16* Qh = smb;
    __nv_bfloat16* Ql = smb + REG;
    __nv_bfloat16* Kh = smb + 2 * REG;
    __nv_bfloat16* Kl = smb + 3 * REG;
    __nv_bfloat16* Vh = smb + 4 * REG;
    __nv_bfloat16* Vl = smb + 5 * REG;

    const int tid  = threadIdx.x;
    const int lane = tid & 31;
    const int warp = tid >> 5;
    const int q0 = blockIdx.x * 64;
    const int h  = blockIdx.y;
    const int b  = blockIdx.z;
    const size_t base = (size_t)b * T_SEQ * N_QKV;
    const int hoff = h * DH;

    const uint32_t sQh = smem_u32(Qh), sQl = smem_u32(Ql);
    const uint32_t sKh = smem_u32(Kh), sKl = smem_u32(Kl);
    const uint32_t sVh = smem_u32(Vh), sVl = smem_u32(Vl);

    // ---- load Q tile [64 x 64] and split ----
    #pragma unroll
    for (int it = 0; it < 8; it++) {
        int idx = it * 128 + tid;
        int r = idx >> 4, d4 = (idx & 15) << 2;
        float4 f = *reinterpret_cast<const float4*>(
            &qkv[base + (size_t)(q0 + r) * N_QKV + hoff + d4]);
        split_store4(f, &Qh[r * AST + d4], &Ql[r * AST + d4]);
    }

    float sa[8][4];          // S / P fragments (8 n-tiles of 8 keys)
    float o[8][4];           // O fragments (8 n-tiles of 8 dims)
    #pragma unroll
    for (int t = 0; t < 8; t++)
        #pragma unroll
        for (int j = 0; j < 4; j++) o[t][j] = 0.f;
    float m0 = -1e20f, m1 = -1e20f, l0 = 0.f, l1 = 0.f;

    const int lane2 = (lane & 3) * 2;
    const int qrow  = warp * 16 + (lane >> 2);          // local query row (lower)
    const int qg0   = q0 + qrow;

    // fragment smem byte-offsets (row part only; k-offset added per step)
    const uint32_t a_off = (uint32_t)((warp * 16 + (lane & 15)) * AST + ((lane >> 4) << 3)) * 2;
    const uint32_t b_off = (uint32_t)(((lane & 7) + ((lane >> 4) << 3)) * AST + (((lane >> 3) & 1) << 3)) * 2;
    const uint32_t v_off = (uint32_t)((lane & 15) * AST + ((lane >> 4) << 3)) * 2;

    for (int c = 0; c < 5; c++) {
        const int kb = q0 - WIN + c * 64;
        __syncthreads();
        // ---- load K/V chunk [64 x 64], split ----
        #pragma unroll
        for (int it = 0; it < 8; it++) {
            int idx = it * 128 + tid;
            int r = idx >> 4, d4 = (idx & 15) << 2;
            int kg = kb + r;
            float4 kf = make_float4(0.f, 0.f, 0.f, 0.f);
            float4 vf = kf;
            if (kg >= 0) {
                const float* p = &qkv[base + (size_t)kg * N_QKV + hoff + d4];
                kf = *reinterpret_cast<const float4*>(p + DM);
                vf = *reinterpret_cast<const float4*>(p + 2 * DM);
            }
            split_store4(kf, &Kh[r * AST + d4], &Kl[r * AST + d4]);
            split_store4(vf, &Vh[r * AST + d4], &Vl[r * AST + d4]);
        }
        __syncthreads();

        // ---- S = Q K^T (3-term bf16x3) ----
        #pragma unroll
        for (int t = 0; t < 8; t++)
            #pragma unroll
            for (int j = 0; j < 4; j++) sa[t][j] = 0.f;

        #pragma unroll
        for (int ks = 0; ks < 4; ks++) {
            uint32_t ah[4], al[4];
            LDM4(ah, sQh + a_off + ks * 32);
            LDM4(al, sQl + a_off + ks * 32);
            #pragma unroll
            for (int np = 0; np < 4; np++) {
                uint32_t bh[4], bl[4];
                uint32_t ko = b_off + (uint32_t)(np * 16 * AST) * 2 + ks * 32;
                LDM4(bh, sKh + ko);
                LDM4(bl, sKl + ko);
                MMA16816(sa[2 * np],     ah, bh[0], bh[1]);
                MMA16816(sa[2 * np],     ah, bl[0], bl[1]);
                MMA16816(sa[2 * np],     al, bh[0], bh[1]);
                MMA16816(sa[2 * np + 1], ah, bh[2], bh[3]);
                MMA16816(sa[2 * np + 1], ah, bl[2], bl[3]);
                MMA16816(sa[2 * np + 1], al, bh[2], bh[3]);
            }
        }

        // ---- mask + online softmax ----
        float mx0 = -1e30f, mx1 = -1e30f;
        #pragma unroll
        for (int t = 0; t < 8; t++) {
            #pragma unroll
            for (int j = 0; j < 4; j++) {
                int col = t * 8 + lane2 + (j & 1);
                int kg  = kb + col;
                int qg  = qg0 + ((j >> 1) << 3);
                bool valid = (kg >= 0) && (kg <= qg) && (kg >= qg - WIN);
                float s = valid ? sa[t][j] * 0.125f : -1e30f;
                sa[t][j] = s;
                if (j < 2) mx0 = fmaxf(mx0, s); else mx1 = fmaxf(mx1, s);
            }
        }
        mx0 = fmaxf(mx0, __shfl_xor_sync(0xffffffffu, mx0, 1));
        mx0 = fmaxf(mx0, __shfl_xor_sync(0xffffffffu, mx0, 2));
        mx1 = fmaxf(mx1, __shfl_xor_sync(0xffffffffu, mx1, 1));
        mx1 = fmaxf(mx1, __shfl_xor_sync(0xffffffffu, mx1, 2));

        const float mn0 = fmaxf(m0, mx0);
        const float mn1 = fmaxf(m1, mx1);
        const float sc0 = __expf(m0 - mn0);
        const float sc1 = __expf(m1 - mn1);
        m0 = mn0; m1 = mn1;

        float ps0 = 0.f, ps1 = 0.f;
        #pragma unroll
        for (int t = 0; t < 8; t++) {
            float p0 = __expf(sa[t][0] - mn0);
            float p1 = __expf(sa[t][1] - mn0);
            float p2 = __expf(sa[t][2] - mn1);
            float p3 = __expf(sa[t][3] - mn1);
            sa[t][0] = p0; sa[t][1] = p1; sa[t][2] = p2; sa[t][3] = p3;
            ps0 += p0 + p1; ps1 += p2 + p3;
        }
        ps0 += __shfl_xor_sync(0xffffffffu, ps0, 1);
        ps0 += __shfl_xor_sync(0xffffffffu, ps0, 2);
        ps1 += __shfl_xor_sync(0xffffffffu, ps1, 1);
        ps1 += __shfl_xor_sync(0xffffffffu, ps1, 2);
        l0 = l0 * sc0 + ps0;
        l1 = l1 * sc1 + ps1;

        #pragma unroll
        for (int t = 0; t < 8; t++) {
            o[t][0] *= sc0; o[t][1] *= sc0;
            o[t][2] *= sc1; o[t][3] *= sc1;
        }

        // ---- O += P V (3-term) ----
        #pragma unroll
        for (int s = 0; s < 4; s++) {
            uint32_t aph[4], apl[4];
            pack2_hilo(sa[2 * s][0],     sa[2 * s][1],     aph[0], apl[0]);
            pack2_hilo(sa[2 * s][2],     sa[2 * s][3],     aph[1], apl[1]);
            pack2_hilo(sa[2 * s + 1][0], sa[2 * s + 1][1], aph[2], apl[2]);
            pack2_hilo(sa[2 * s + 1][2], sa[2 * s + 1][3], aph[3], apl[3]);
            #pragma unroll
            for (int nd = 0; nd < 4; nd++) {
                uint32_t vh[4], vl[4];
                uint32_t vo = v_off + (uint32_t)(s * 16 * AST) * 2 + nd * 32;
                LDM4T(vh, sVh + vo);
                LDM4T(vl, sVl + vo);
                MMA16816(o[2 * nd],     aph, vh[0], vh[1]);
                MMA16816(o[2 * nd],     aph, vl[0], vl[1]);
                MMA16816(o[2 * nd],     apl, vh[0], vh[1]);
                MMA16816(o[2 * nd + 1], aph, vh[2], vh[3]);
                MMA16816(o[2 * nd + 1], aph, vl[2], vl[3]);
                MMA16816(o[2 * nd + 1], apl, vh[2], vh[3]);
            }
        }
    }

    // ---- epilogue: normalize, split to bf16 hi/lo, store ----
    const float il0 = 1.f / l0;
    const float il1 = 1.f / l1;
    const size_t row0 = (size_t)(b * T_SEQ + qg0);
    #pragma unroll
    for (int t = 0; t < 8; t++) {
        int col = hoff + t * 8 + lane2;
        uint32_t h0, lo0, h1, lo1;
        pack2_hilo(o[t][0] * il0, o[t][1] * il0, h0, lo0);
        pack2_hilo(o[t][2] * il1, o[t][3] * il1, h1, lo1);
        *reinterpret_cast<uint32_t*>(&out_hi[row0 * DM + col])       = h0;
        *reinterpret_cast<uint32_t*>(&out_lo[row0 * DM + col])       = lo0;
        *reinterpret_cast<uint32_t*>(&out_hi[(row0 + 8) * DM + col]) = h1;
        *reinterpret_cast<uint32_t*>(&out_lo[(row0 + 8) * DM + col]) = lo1;
    }
}

// ---------------------------------------------------------------------------
extern "C" void kernel_launch(void* const* d_in, const int* in_sizes, int n_in,
                              void* d_out, int out_size) {
    const float* x     = (const float*)d_in[0];   // [4,2048,1024]
    const float* w_qkv = (const float*)d_in[1];   // [1024,3072]
    const float* w_out = (const float*)d_in[2];   // [1024,1024]
    float* out = (float*)d_out;                   // [4,2048,1024]

    __nv_bfloat16 *x_hi, *x_lo, *wq_hi, *wq_lo, *wo_hi, *wo_lo, *at_hi, *at_lo;
    float *qkv_buf;
    cudaGetSymbolAddress((void**)&x_hi,  g_x_hi);
    cudaGetSymbolAddress((void**)&x_lo,  g_x_lo);
    cudaGetSymbolAddress((void**)&wq_hi, g_wqkvT_hi);
    cudaGetSymbolAddress((void**)&wq_lo, g_wqkvT_lo);
    cudaGetSymbolAddress((void**)&wo_hi, g_woutT_hi);
    cudaGetSymbolAddress((void**)&wo_lo, g_woutT_lo);
    cudaGetSymbolAddress((void**)&at_hi, g_att_hi);
    cudaGetSymbolAddress((void**)&at_lo, g_att_lo);
    cudaGetSymbolAddress((void**)&qkv_buf, g_qkv);

    const int GEMM_SMEM = 2 * 4 * BM * LDS_K * (int)sizeof(__nv_bfloat16);  // 81920
    cudaFuncSetAttribute(gemm_bf16x3, cudaFuncAttributeMaxDynamicSharedMemorySize, GEMM_SMEM);
    const int ATTN_SMEM = 6 * 64 * AST * (int)sizeof(__nv_bfloat16);        // 55296
    cudaFuncSetAttribute(attn_tc_kernel, cudaFuncAttributeMaxDynamicSharedMemorySize, ATTN_SMEM);

    // 0) precision splits / weight transposes
    {
        int n4 = M_ROWS * DM / 4;
        split_kernel<<<(n4 + 255) / 256, 256>>>(x, x_hi, x_lo, n4);
        dim3 g1(N_QKV / 32, DM / 32);
        transpose_split_kernel<<<g1, 256>>>(w_qkv, wq_hi, wq_lo, DM, N_QKV);
        dim3 g2(DM / 32, DM / 32);
        transpose_split_kernel<<<g2, 256>>>(w_out, wo_hi, wo_lo, DM, DM);
    }
    // 1) QKV projection
    {
        dim3 grid(N_QKV / BN, M_ROWS / BM);
        gemm_bf16x3<<<grid, 256, GEMM_SMEM>>>(x_hi, x_lo, wq_hi, wq_lo,
                                              qkv_buf, M_ROWS, N_QKV, DM);
    }
    // 2) tensor-core sliding-window attention (writes bf16 hi/lo directly)
    {
        dim3 grid(T_SEQ / 64, NH, B_SZ);
        attn_tc_kernel<<<grid, 128, ATTN_SMEM>>>(qkv_buf, at_hi, at_lo);
    }
    // 3) output projection
    {
        dim3 grid(DM / BN, M_ROWS / BM);
        gemm_bf16x3<<<grid, 256, GEMM_SMEM>>>(at_hi, at_lo, wo_hi, wo_lo,
                                              out, M_ROWS, DM, DM);
    }
}

// round 5
// speedup vs baseline: 4.3794x; 1.1641x over previous
#include <cuda_runtime.h>
#include <cuda_bf16.h>
#include <math.h>
#include <stdint.h>

// Problem constants
#define B_SZ   4
#define T_SEQ  2048
#define DM     1024
#define NH     16
#define DH     64
#define WIN    256
#define M_ROWS (B_SZ * T_SEQ)        // 8192
#define N_QKV  (3 * DM)              // 3072

// GEMM tiling
#define BM 128
#define BN 128
#define BKK 32
#define PAD 8
#define LDS_K (BKK + PAD)            // 40 bf16 elems per row

// ---------------------------------------------------------------------------
// Device scratch (allocation-free per harness rules)
// ---------------------------------------------------------------------------
__device__ __align__(16) __nv_bfloat16 g_x_hi[M_ROWS * (size_t)DM];
__device__ __align__(16) __nv_bfloat16 g_x_lo[M_ROWS * (size_t)DM];
__device__ __align__(16) __nv_bfloat16 g_wqkvT_hi[N_QKV * (size_t)DM];   // [N][K]
__device__ __align__(16) __nv_bfloat16 g_wqkvT_lo[N_QKV * (size_t)DM];
__device__ __align__(16) __nv_bfloat16 g_woutT_hi[DM * (size_t)DM];      // [N][K]
__device__ __align__(16) __nv_bfloat16 g_woutT_lo[DM * (size_t)DM];
__device__ __align__(16) float g_qkv[M_ROWS * (size_t)N_QKV];            // [8192,3072]
__device__ __align__(16) __nv_bfloat16 g_att_hi[M_ROWS * (size_t)DM];
__device__ __align__(16) __nv_bfloat16 g_att_lo[M_ROWS * (size_t)DM];

// ---------------------------------------------------------------------------
// Helpers
// ---------------------------------------------------------------------------
__device__ __forceinline__ uint32_t smem_u32(const void* p) {
    return (uint32_t)__cvta_generic_to_shared(p);
}

#define CP16(saddr, gptr) \
    asm volatile("cp.async.cg.shared.global [%0], [%1], 16;" :: "r"(saddr), "l"(gptr))
#define CP_COMMIT() asm volatile("cp.async.commit_group;")
#define CP_WAIT(n)  asm volatile("cp.async.wait_group %0;" :: "n"(n))

#define LDM4(r, addr) \
    asm volatile("ldmatrix.sync.aligned.m8n8.x4.shared.b16 {%0,%1,%2,%3}, [%4];" \
        : "=r"((r)[0]), "=r"((r)[1]), "=r"((r)[2]), "=r"((r)[3]) : "r"(addr))

#define LDM4T(r, addr) \
    asm volatile("ldmatrix.sync.aligned.m8n8.x4.trans.shared.b16 {%0,%1,%2,%3}, [%4];" \
        : "=r"((r)[0]), "=r"((r)[1]), "=r"((r)[2]), "=r"((r)[3]) : "r"(addr))

#define MMA16816(d, a, b0, b1) \
    asm volatile("mma.sync.aligned.m16n8k16.row.col.f32.bf16.bf16.f32 " \
        "{%0,%1,%2,%3}, {%4,%5,%6,%7}, {%8,%9}, {%0,%1,%2,%3};" \
        : "+f"((d)[0]), "+f"((d)[1]), "+f"((d)[2]), "+f"((d)[3]) \
        : "r"((a)[0]), "r"((a)[1]), "r"((a)[2]), "r"((a)[3]), "r"(b0), "r"(b1))

__device__ __forceinline__ void split_f32(float f, __nv_bfloat16& hi, __nv_bfloat16& lo) {
    hi = __float2bfloat16_rn(f);
    lo = __float2bfloat16_rn(f - __bfloat162float(hi));
}

__device__ __forceinline__ void pack2_hilo(float x, float y, uint32_t& h, uint32_t& l) {
    __nv_bfloat162 hv, lv;
    split_f32(x, hv.x, lv.x);
    split_f32(y, hv.y, lv.y);
    h = *reinterpret_cast<uint32_t*>(&hv);
    l = *reinterpret_cast<uint32_t*>(&lv);
}

__device__ __forceinline__ void split_store4(float4 f, __nv_bfloat16* hp, __nv_bfloat16* lp) {
    __nv_bfloat162 h01, l01, h23, l23;
    split_f32(f.x, h01.x, l01.x);
    split_f32(f.y, h01.y, l01.y);
    split_f32(f.z, h23.x, l23.x);
    split_f32(f.w, h23.y, l23.y);
    *reinterpret_cast<__nv_bfloat162*>(hp)     = h01;
    *reinterpret_cast<__nv_bfloat162*>(hp + 2) = h23;
    *reinterpret_cast<__nv_bfloat162*>(lp)     = l01;
    *reinterpret_cast<__nv_bfloat162*>(lp + 2) = l23;
}

// ---------------------------------------------------------------------------
// prep kernels
// ---------------------------------------------------------------------------
__global__ void split_kernel(const float* __restrict__ src,
                             __nv_bfloat16* __restrict__ hi,
                             __nv_bfloat16* __restrict__ lo, int n4) {
    int i = blockIdx.x * blockDim.x + threadIdx.x;
    if (i >= n4) return;
    float4 f = reinterpret_cast<const float4*>(src)[i];
    split_store4(f, hi + i * 4, lo + i * 4);
}

__global__ void transpose_split_kernel(const float* __restrict__ src,
                                       __nv_bfloat16* __restrict__ hi,
                                       __nv_bfloat16* __restrict__ lo,
                                       int K, int N) {
    __shared__ float t[32][33];
    const int n0 = blockIdx.x * 32;
    const int k0 = blockIdx.y * 32;
    const int tx = threadIdx.x & 31;
    const int ty = threadIdx.x >> 5;
    #pragma unroll
    for (int i = 0; i < 32; i += 8)
        t[ty + i][tx] = src[(size_t)(k0 + ty + i) * N + n0 + tx];
    __syncthreads();
    #pragma unroll
    for (int i = 0; i < 32; i += 8) {
        float f = t[tx][ty + i];
        __nv_bfloat16 h, l;
        split_f32(f, h, l);
        size_t o = (size_t)(n0 + ty + i) * K + k0 + tx;
        hi[o] = h;
        lo[o] = l;
    }
}

// ---------------------------------------------------------------------------
// bf16x3 GEMM: C[M][N] fp32 = A @ B^T (Bt is [N][K]).
// 128x128x32 tiles, 8 warps. MMAs reordered so consecutive MMAs never hit
// the same accumulator (reuse distance 4); launch_bounds(256,2) for 2 CTAs/SM.
// ---------------------------------------------------------------------------
__global__ __launch_bounds__(256, 2)
void gemm_bf16x3(const __nv_bfloat16* __restrict__ Ah, const __nv_bfloat16* __restrict__ Al,
                 const __nv_bfloat16* __restrict__ Bh, const __nv_bfloat16* __restrict__ Bl,
                 float* __restrict__ C, int M, int N, int K) {
    extern __shared__ __nv_bfloat16 sm[];
    const int SSZ = 4 * BM * LDS_K;
    const int AH_B = 0;
    const int AL_B = BM * LDS_K * 2;
    const int BH_B = 2 * BM * LDS_K * 2;
    const int BL_B = 3 * BM * LDS_K * 2;

    const int tid  = threadIdx.x;
    const int lane = tid & 31;
    const int warp = tid >> 5;
    const int wm   = warp & 3;
    const int wn   = warp >> 2;
    const int m0   = blockIdx.y * BM;
    const int n0   = blockIdx.x * BN;

    const uint32_t s0 = smem_u32(sm);
    const uint32_t s1 = smem_u32(sm + SSZ);

    const int lr = tid >> 2;
    const int lk = (tid & 3) * 8;

    float acc[2][8][4];
    #pragma unroll
    for (int a = 0; a < 2; a++)
        #pragma unroll
        for (int b = 0; b < 8; b++)
            #pragma unroll
            for (int c = 0; c < 4; c++) acc[a][b][c] = 0.f;

    const int NK = K / BKK;

    auto load_stage = [&](uint32_t sbase, int kt) {
        #pragma unroll
        for (int it = 0; it < 2; ++it) {
            int row = lr + it * 64;
            uint32_t so = (uint32_t)(row * LDS_K + lk) * 2;
            size_t ga = (size_t)(m0 + row) * K + kt + lk;
            size_t gb = (size_t)(n0 + row) * K + kt + lk;
            CP16(sbase + AH_B + so, Ah + ga);
            CP16(sbase + AL_B + so, Al + ga);
            CP16(sbase + BH_B + so, Bh + gb);
            CP16(sbase + BL_B + so, Bl + gb);
        }
    };

    load_stage(s0, 0);
    CP_COMMIT();

    const int a_row = wm * 32 + (lane & 15);
    const int a_coloff = (lane >> 4) << 3;
    const int b_row = wn * 64 + (lane & 7) + ((lane >> 4) << 3);
    const int b_koff = ((lane >> 3) & 1) << 3;

    for (int kt = 0; kt < NK; ++kt) {
        uint32_t scur = (kt & 1) ? s1 : s0;
        uint32_t snxt = (kt & 1) ? s0 : s1;
        if (kt + 1 < NK) {
            load_stage(snxt, (kt + 1) * BKK);
            CP_COMMIT();
            CP_WAIT(1);
        } else {
            CP_WAIT(0);
        }
        __syncthreads();

        #pragma unroll
        for (int ks = 0; ks < 2; ++ks) {
            uint32_t ah[2][4], al[2][4];
            #pragma unroll
            for (int mt = 0; mt < 2; ++mt) {
                uint32_t ad = scur + (uint32_t)((a_row + mt * 16) * LDS_K
                                                + ks * 16 + a_coloff) * 2;
                LDM4(ah[mt], ad + AH_B);
                LDM4(al[mt], ad + AL_B);
            }
            #pragma unroll
            for (int np = 0; np < 4; ++np) {
                uint32_t bd = scur + (uint32_t)((b_row + np * 16) * LDS_K
                                                + ks * 16 + b_koff) * 2;
                uint32_t bh[4], bl[4];
                LDM4(bh, bd + BH_B);
                LDM4(bl, bd + BL_B);
                // 12 MMAs, accumulator reuse distance = 4
                // pass 1: hi*hi
                MMA16816(acc[0][2 * np],     ah[0], bh[0], bh[1]);
                MMA16816(acc[1][2 * np],     ah[1], bh[0], bh[1]);
                MMA16816(acc[0][2 * np + 1], ah[0], bh[2], bh[3]);
                MMA16816(acc[1][2 * np + 1], ah[1], bh[2], bh[3]);
                // pass 2: hi*lo
                MMA16816(acc[0][2 * np],     ah[0], bl[0], bl[1]);
                MMA16816(acc[1][2 * np],     ah[1], bl[0], bl[1]);
                MMA16816(acc[0][2 * np + 1], ah[0], bl[2], bl[3]);
                MMA16816(acc[1][2 * np + 1], ah[1], bl[2], bl[3]);
                // pass 3: lo*hi
                MMA16816(acc[0][2 * np],     al[0], bh[0], bh[1]);
                MMA16816(acc[1][2 * np],     al[1], bh[0], bh[1]);
                MMA16816(acc[0][2 * np + 1], al[0], bh[2], bh[3]);
                MMA16816(acc[1][2 * np + 1], al[1], bh[2], bh[3]);
            }
        }
        __syncthreads();
    }

    #pragma unroll
    for (int mt = 0; mt < 2; ++mt) {
        #pragma unroll
        for (int nt = 0; nt < 8; ++nt) {
            int row = m0 + wm * 32 + mt * 16 + (lane >> 2);
            int col = n0 + wn * 64 + nt * 8 + (lane & 3) * 2;
            float2 v0 = make_float2(acc[mt][nt][0], acc[mt][nt][1]);
            float2 v1 = make_float2(acc[mt][nt][2], acc[mt][nt][3]);
            *reinterpret_cast<float2*>(&C[(size_t)row * N + col]) = v0;
            *reinterpret_cast<float2*>(&C[(size_t)(row + 8) * N + col]) = v1;
        }
    }
}

// ---------------------------------------------------------------------------
// Tensor-core sliding-window attention (bf16x3, mma.sync), MMAs reordered.
// ---------------------------------------------------------------------------
#define AST 72

__global__ __launch_bounds__(128, 4)
void attn_tc_kernel(const float* __restrict__ qkv,
                    __nv_bfloat16* __restrict__ out_hi,
                    __nv_bfloat16* __restrict__ out_lo) {
    extern __shared__ __nv_bfloat16 smb[];
    const int REG = 64 * AST;
    __nv_bfloat16* Qh = smb;
    __nv_bfloat16* Ql = smb + REG;
    __nv_bfloat16* Kh = smb + 2 * REG;
    __nv_bfloat16* Kl = smb + 3 * REG;
    __nv_bfloat16* Vh = smb + 4 * REG;
    __nv_bfloat16* Vl = smb + 5 * REG;

    const int tid  = threadIdx.x;
    const int lane = tid & 31;
    const int warp = tid >> 5;
    const int q0 = blockIdx.x * 64;
    const int h  = blockIdx.y;
    const int b  = blockIdx.z;
    const size_t base = (size_t)b * T_SEQ * N_QKV;
    const int hoff = h * DH;

    const uint32_t sQh = smem_u32(Qh), sQl = smem_u32(Ql);
    const uint32_t sKh = smem_u32(Kh), sKl = smem_u32(Kl);
    const uint32_t sVh = smem_u32(Vh), sVl = smem_u32(Vl);

    #pragma unroll
    for (int it = 0; it < 8; it++) {
        int idx = it * 128 + tid;
        int r = idx >> 4, d4 = (idx & 15) << 2;
        float4 f = *reinterpret_cast<const float4*>(
            &qkv[base + (size_t)(q0 + r) * N_QKV + hoff + d4]);
        split_store4(f, &Qh[r * AST + d4], &Ql[r * AST + d4]);
    }

    float sa[8][4];
    float o[8][4];
    #pragma unroll
    for (int t = 0; t < 8; t++)
        #pragma unroll
        for (int j = 0; j < 4; j++) o[t][j] = 0.f;
    float m0 = -1e20f, m1 = -1e20f, l0 = 0.f, l1 = 0.f;

    const int lane2 = (lane & 3) * 2;
    const int qrow  = warp * 16 + (lane >> 2);
    const int qg0   = q0 + qrow;

    const uint32_t a_off = (uint32_t)((warp * 16 + (lane & 15)) * AST + ((lane >> 4) << 3)) * 2;
    const uint32_t b_off = (uint32_t)(((lane & 7) + ((lane >> 4) << 3)) * AST + (((lane >> 3) & 1) << 3)) * 2;
    const uint32_t v_off = (uint32_t)((lane & 15) * AST + ((lane >> 4) << 3)) * 2;

    for (int c = 0; c < 5; c++) {
        const int kb = q0 - WIN + c * 64;
        __syncthreads();
        #pragma unroll
        for (int it = 0; it < 8; it++) {
            int idx = it * 128 + tid;
            int r = idx >> 4, d4 = (idx & 15) << 2;
            int kg = kb + r;
            float4 kf = make_float4(0.f, 0.f, 0.f, 0.f);
            float4 vf = kf;
            if (kg >= 0) {
                const float* p = &qkv[base + (size_t)kg * N_QKV + hoff + d4];
                kf = *reinterpret_cast<const float4*>(p + DM);
                vf = *reinterpret_cast<const float4*>(p + 2 * DM);
            }
            split_store4(kf, &Kh[r * AST + d4], &Kl[r * AST + d4]);
            split_store4(vf, &Vh[r * AST + d4], &Vl[r * AST + d4]);
        }
        __syncthreads();

        #pragma unroll
        for (int t = 0; t < 8; t++)
            #pragma unroll
            for (int j = 0; j < 4; j++) sa[t][j] = 0.f;

        #pragma unroll
        for (int ks = 0; ks < 4; ks++) {
            uint32_t ah[4], al[4];
            LDM4(ah, sQh + a_off + ks * 32);
            LDM4(al, sQl + a_off + ks * 32);
            #pragma unroll
            for (int np = 0; np < 4; np++) {
                uint32_t bh[4], bl[4];
                uint32_t ko = b_off + (uint32_t)(np * 16 * AST) * 2 + ks * 32;
                LDM4(bh, sKh + ko);
                LDM4(bl, sKl + ko);
                // reuse distance 2 (chains broken up)
                MMA16816(sa[2 * np],     ah, bh[0], bh[1]);
                MMA16816(sa[2 * np + 1], ah, bh[2], bh[3]);
                MMA16816(sa[2 * np],     ah, bl[0], bl[1]);
                MMA16816(sa[2 * np + 1], ah, bl[2], bl[3]);
                MMA16816(sa[2 * np],     al, bh[0], bh[1]);
                MMA16816(sa[2 * np + 1], al, bh[2], bh[3]);
            }
        }

        float mx0 = -1e30f, mx1 = -1e30f;
        #pragma unroll
        for (int t = 0; t < 8; t++) {
            #pragma unroll
            for (int j = 0; j < 4; j++) {
                int col = t * 8 + lane2 + (j & 1);
                int kg  = kb + col;
                int qg  = qg0 + ((j >> 1) << 3);
                bool valid = (kg >= 0) && (kg <= qg) && (kg >= qg - WIN);
                float s = valid ? sa[t][j] * 0.125f : -1e30f;
                sa[t][j] = s;
                if (j < 2) mx0 = fmaxf(mx0, s); else mx1 = fmaxf(mx1, s);
            }
        }
        mx0 = fmaxf(mx0, __shfl_xor_sync(0xffffffffu, mx0, 1));
        mx0 = fmaxf(mx0, __shfl_xor_sync(0xffffffffu, mx0, 2));
        mx1 = fmaxf(mx1, __shfl_xor_sync(0xffffffffu, mx1, 1));
        mx1 = fmaxf(mx1, __shfl_xor_sync(0xffffffffu, mx1, 2));

        const float mn0 = fmaxf(m0, mx0);
        const float mn1 = fmaxf(m1, mx1);
        const float sc0 = __expf(m0 - mn0);
        const float sc1 = __expf(m1 - mn1);
        m0 = mn0; m1 = mn1;

        float ps0 = 0.f, ps1 = 0.f;
        #pragma unroll
        for (int t = 0; t < 8; t++) {
            float p0 = __expf(sa[t][0] - mn0);
            float p1 = __expf(sa[t][1] - mn0);
            float p2 = __expf(sa[t][2] - mn1);
            float p3 = __expf(sa[t][3] - mn1);
            sa[t][0] = p0; sa[t][1] = p1; sa[t][2] = p2; sa[t][3] = p3;
            ps0 += p0 + p1; ps1 += p2 + p3;
        }
        ps0 += __shfl_xor_sync(0xffffffffu, ps0, 1);
        ps0 += __shfl_xor_sync(0xffffffffu, ps0, 2);
        ps1 += __shfl_xor_sync(0xffffffffu, ps1, 1);
        ps1 += __shfl_xor_sync(0xffffffffu, ps1, 2);
        l0 = l0 * sc0 + ps0;
        l1 = l1 * sc1 + ps1;

        #pragma unroll
        for (int t = 0; t < 8; t++) {
            o[t][0] *= sc0; o[t][1] *= sc0;
            o[t][2] *= sc1; o[t][3] *= sc1;
        }

        #pragma unroll
        for (int s = 0; s < 4; s++) {
            uint32_t aph[4], apl[4];
            pack2_hilo(sa[2 * s][0],     sa[2 * s][1],     aph[0], apl[0]);
            pack2_hilo(sa[2 * s][2],     sa[2 * s][3],     aph[1], apl[1]);
            pack2_hilo(sa[2 * s + 1][0], sa[2 * s + 1][1], aph[2], apl[2]);
            pack2_hilo(sa[2 * s + 1][2], sa[2 * s + 1][3], aph[3], apl[3]);
            #pragma unroll
            for (int nd = 0; nd < 4; nd++) {
                uint32_t vh[4], vl[4];
                uint32_t vo = v_off + (uint32_t)(s * 16 * AST) * 2 + nd * 32;
                LDM4T(vh, sVh + vo);
                LDM4T(vl, sVl + vo);
                // reuse distance 2
                MMA16816(o[2 * nd],     aph, vh[0], vh[1]);
                MMA16816(o[2 * nd + 1], aph, vh[2], vh[3]);
                MMA16816(o[2 * nd],     aph, vl[0], vl[1]);
                MMA16816(o[2 * nd + 1], aph, vl[2], vl[3]);
                MMA16816(o[2 * nd],     apl, vh[0], vh[1]);
                MMA16816(o[2 * nd + 1], apl, vh[2], vh[3]);
            }
        }
    }

    const float il0 = 1.f / l0;
    const float il1 = 1.f / l1;
    const size_t row0 = (size_t)(b * T_SEQ + qg0);
    #pragma unroll
    for (int t = 0; t < 8; t++) {
        int col = hoff + t * 8 + lane2;
        uint32_t h0, lo0, h1, lo1;
        pack2_hilo(o[t][0] * il0, o[t][1] * il0, h0, lo0);
        pack2_hilo(o[t][2] * il1, o[t][3] * il1, h1, lo1);
        *reinterpret_cast<uint32_t*>(&out_hi[row0 * DM + col])       = h0;
        *reinterpret_cast<uint32_t*>(&out_lo[row0 * DM + col])       = lo0;
        *reinterpret_cast<uint32_t*>(&out_hi[(row0 + 8) * DM + col]) = h1;
        *reinterpret_cast<uint32_t*>(&out_lo[(row0 + 8) * DM + col]) = lo1;
    }
}

// ---------------------------------------------------------------------------
extern "C" void kernel_launch(void* const* d_in, const int* in_sizes, int n_in,
                              void* d_out, int out_size) {
    const float* x     = (const float*)d_in[0];
    const float* w_qkv = (const float*)d_in[1];
    const float* w_out = (const float*)d_in[2];
    float* out = (float*)d_out;

    __nv_bfloat16 *x_hi, *x_lo, *wq_hi, *wq_lo, *wo_hi, *wo_lo, *at_hi, *at_lo;
    float *qkv_buf;
    cudaGetSymbolAddress((void**)&x_hi,  g_x_hi);
    cudaGetSymbolAddress((void**)&x_lo,  g_x_lo);
    cudaGetSymbolAddress((void**)&wq_hi, g_wqkvT_hi);
    cudaGetSymbolAddress((void**)&wq_lo, g_wqkvT_lo);
    cudaGetSymbolAddress((void**)&wo_hi, g_woutT_hi);
    cudaGetSymbolAddress((void**)&wo_lo, g_woutT_lo);
    cudaGetSymbolAddress((void**)&at_hi, g_att_hi);
    cudaGetSymbolAddress((void**)&at_lo, g_att_lo);
    cudaGetSymbolAddress((void**)&qkv_buf, g_qkv);

    const int GEMM_SMEM = 2 * 4 * BM * LDS_K * (int)sizeof(__nv_bfloat16);  // 81920
    cudaFuncSetAttribute(gemm_bf16x3, cudaFuncAttributeMaxDynamicSharedMemorySize, GEMM_SMEM);
    const int ATTN_SMEM = 6 * 64 * AST * (int)sizeof(__nv_bfloat16);        // 55296
    cudaFuncSetAttribute(attn_tc_kernel, cudaFuncAttributeMaxDynamicSharedMemorySize, ATTN_SMEM);

    // 0) precision splits / weight transposes
    {
        int n4 = M_ROWS * DM / 4;
        split_kernel<<<(n4 + 255) / 256, 256>>>(x, x_hi, x_lo, n4);
        dim3 g1(N_QKV / 32, DM / 32);
        transpose_split_kernel<<<g1, 256>>>(w_qkv, wq_hi, wq_lo, DM, N_QKV);
        dim3 g2(DM / 32, DM / 32);
        transpose_split_kernel<<<g2, 256>>>(w_out, wo_hi, wo_lo, DM, DM);
    }
    // 1) QKV projection
    {
        dim3 grid(N_QKV / BN, M_ROWS / BM);
        gemm_bf16x3<<<grid, 256, GEMM_SMEM>>>(x_hi, x_lo, wq_hi, wq_lo,
                                              qkv_buf, M_ROWS, N_QKV, DM);
    }
    // 2) attention
    {
        dim3 grid(T_SEQ / 64, NH, B_SZ);
        attn_tc_kernel<<<grid, 128, ATTN_SMEM>>>(qkv_buf, at_hi, at_lo);
    }
    // 3) output projection
    {
        dim3 grid(DM / BN, M_ROWS / BM);
        gemm_bf16x3<<<grid, 256, GEMM_SMEM>>>(at_hi, at_lo, wo_hi, wo_lo,
                                              out, M_ROWS, DM, DM);
    }
}

// round 6
// speedup vs baseline: 5.0017x; 1.1421x over previous
#include <cuda_runtime.h>
#include <cuda_bf16.h>
#include <math.h>
#include <stdint.h>

// Problem constants
#define B_SZ   4
#define T_SEQ  2048
#define DM     1024
#define NH     16
#define DH     64
#define WIN    256
#define M_ROWS (B_SZ * T_SEQ)        // 8192
#define N_QKV  (3 * DM)              // 3072

// GEMM tiling
#define BM 128
#define BN 128
#define BKK 32                        // K elems per stage
#define NSTAGE 3
#define TILE_B (BM * 64)              // one split tile: 128 rows x 64B = 8192 B
#define STG_B  (4 * TILE_B)           // Ah,Al,Bh,Bl = 32768 B
#define GEMM_SMEM (NSTAGE * STG_B + 128)

// ---------------------------------------------------------------------------
// Device scratch (allocation-free per harness rules)
// ---------------------------------------------------------------------------
__device__ __align__(16) __nv_bfloat16 g_x_hi[M_ROWS * (size_t)DM];
__device__ __align__(16) __nv_bfloat16 g_x_lo[M_ROWS * (size_t)DM];
__device__ __align__(16) __nv_bfloat16 g_wqkvT_hi[N_QKV * (size_t)DM];   // [N][K]
__device__ __align__(16) __nv_bfloat16 g_wqkvT_lo[N_QKV * (size_t)DM];
__device__ __align__(16) __nv_bfloat16 g_woutT_hi[DM * (size_t)DM];      // [N][K]
__device__ __align__(16) __nv_bfloat16 g_woutT_lo[DM * (size_t)DM];
__device__ __align__(16) float g_qkv[M_ROWS * (size_t)N_QKV];            // [8192,3072]
__device__ __align__(16) __nv_bfloat16 g_att_hi[M_ROWS * (size_t)DM];
__device__ __align__(16) __nv_bfloat16 g_att_lo[M_ROWS * (size_t)DM];

// ---------------------------------------------------------------------------
// Helpers
// ---------------------------------------------------------------------------
__device__ __forceinline__ uint32_t smem_u32(const void* p) {
    return (uint32_t)__cvta_generic_to_shared(p);
}

#define CP16(saddr, gptr) \
    asm volatile("cp.async.cg.shared.global [%0], [%1], 16;" :: "r"(saddr), "l"(gptr))
#define CP_COMMIT() asm volatile("cp.async.commit_group;")
#define CP_WAIT(n)  asm volatile("cp.async.wait_group %0;" :: "n"(n))

#define LDM4(r, addr) \
    asm volatile("ldmatrix.sync.aligned.m8n8.x4.shared.b16 {%0,%1,%2,%3}, [%4];" \
        : "=r"((r)[0]), "=r"((r)[1]), "=r"((r)[2]), "=r"((r)[3]) : "r"(addr))

#define LDM4T(r, addr) \
    asm volatile("ldmatrix.sync.aligned.m8n8.x4.trans.shared.b16 {%0,%1,%2,%3}, [%4];" \
        : "=r"((r)[0]), "=r"((r)[1]), "=r"((r)[2]), "=r"((r)[3]) : "r"(addr))

#define MMA16816(d, a, b0, b1) \
    asm volatile("mma.sync.aligned.m16n8k16.row.col.f32.bf16.bf16.f32 " \
        "{%0,%1,%2,%3}, {%4,%5,%6,%7}, {%8,%9}, {%0,%1,%2,%3};" \
        : "+f"((d)[0]), "+f"((d)[1]), "+f"((d)[2]), "+f"((d)[3]) \
        : "r"((a)[0]), "r"((a)[1]), "r"((a)[2]), "r"((a)[3]), "r"(b0), "r"(b1))

// 64B-row swizzle: chunk' = chunk ^ ((row>>1)&3); off = row*64 + chunk*16
#define SWZ2(off) ((off) ^ ((((off) >> 7) & 3u) << 4))

__device__ __forceinline__ void split_f32(float f, __nv_bfloat16& hi, __nv_bfloat16& lo) {
    hi = __float2bfloat16_rn(f);
    lo = __float2bfloat16_rn(f - __bfloat162float(hi));
}

__device__ __forceinline__ void pack2_hilo(float x, float y, uint32_t& h, uint32_t& l) {
    __nv_bfloat162 hv, lv;
    split_f32(x, hv.x, lv.x);
    split_f32(y, hv.y, lv.y);
    h = *reinterpret_cast<uint32_t*>(&hv);
    l = *reinterpret_cast<uint32_t*>(&lv);
}

__device__ __forceinline__ void split_store4(float4 f, __nv_bfloat16* hp, __nv_bfloat16* lp) {
    __nv_bfloat162 h01, l01, h23, l23;
    split_f32(f.x, h01.x, l01.x);
    split_f32(f.y, h01.y, l01.y);
    split_f32(f.z, h23.x, l23.x);
    split_f32(f.w, h23.y, l23.y);
    *reinterpret_cast<__nv_bfloat162*>(hp)     = h01;
    *reinterpret_cast<__nv_bfloat162*>(hp + 2) = h23;
    *reinterpret_cast<__nv_bfloat162*>(lp)     = l01;
    *reinterpret_cast<__nv_bfloat162*>(lp + 2) = l23;
}

// ---------------------------------------------------------------------------
// prep kernels
// ---------------------------------------------------------------------------
__global__ void split_kernel(const float* __restrict__ src,
                             __nv_bfloat16* __restrict__ hi,
                             __nv_bfloat16* __restrict__ lo, int n4) {
    int i = blockIdx.x * blockDim.x + threadIdx.x;
    if (i >= n4) return;
    float4 f = reinterpret_cast<const float4*>(src)[i];
    split_store4(f, hi + i * 4, lo + i * 4);
}

__global__ void transpose_split_kernel(const float* __restrict__ src,
                                       __nv_bfloat16* __restrict__ hi,
                                       __nv_bfloat16* __restrict__ lo,
                                       int K, int N) {
    __shared__ float t[32][33];
    const int n0 = blockIdx.x * 32;
    const int k0 = blockIdx.y * 32;
    const int tx = threadIdx.x & 31;
    const int ty = threadIdx.x >> 5;
    #pragma unroll
    for (int i = 0; i < 32; i += 8)
        t[ty + i][tx] = src[(size_t)(k0 + ty + i) * N + n0 + tx];
    __syncthreads();
    #pragma unroll
    for (int i = 0; i < 32; i += 8) {
        float f = t[tx][ty + i];
        __nv_bfloat16 h, l;
        split_f32(f, h, l);
        size_t o = (size_t)(n0 + ty + i) * K + k0 + tx;
        hi[o] = h;
        lo[o] = l;
    }
}

// ---------------------------------------------------------------------------
// bf16x3 GEMM: C[M][N] fp32 = A @ B^T (Bt is [N][K]).
// 128x128x32 tiles, 8 warps, 3-stage cp.async ring, ONE syncthreads per
// K-tile, XOR-swizzled 64B rows (no pad), reuse-distance-4 MMA order.
// ---------------------------------------------------------------------------
__global__ __launch_bounds__(256, 2)
void gemm_bf16x3(const __nv_bfloat16* __restrict__ Ah, const __nv_bfloat16* __restrict__ Al,
                 const __nv_bfloat16* __restrict__ Bh, const __nv_bfloat16* __restrict__ Bl,
                 float* __restrict__ C, int M, int N, int K) {
    extern __shared__ char smraw[];
    const uint32_t sbase = (smem_u32(smraw) + 127) & ~127u;

    const int tid  = threadIdx.x;
    const int lane = tid & 31;
    const int warp = tid >> 5;
    const int wm   = warp & 3;
    const int wn   = warp >> 2;
    const int m0   = blockIdx.y * BM;
    const int n0   = blockIdx.x * BN;

    float acc[2][8][4];
    #pragma unroll
    for (int a = 0; a < 2; a++)
        #pragma unroll
        for (int b = 0; b < 8; b++)
            #pragma unroll
            for (int c = 0; c < 4; c++) acc[a][b][c] = 0.f;

    const int NK = K / BKK;

    // loader: 512 16B-chunks per tile, 2 per thread per tile
    auto load_stage = [&](int buf, int kt) {
        const uint32_t s = sbase + buf * STG_B;
        const int kg = kt * BKK;
        #pragma unroll
        for (int i = 0; i < 2; ++i) {
            int cg  = tid + i * 256;
            int row = cg >> 2;
            int ck  = cg & 3;
            uint32_t so = SWZ2((uint32_t)(row * 64 + ck * 16));
            size_t ka = (size_t)kg + ck * 8;
            size_t ga = (size_t)(m0 + row) * K + ka;
            size_t gb = (size_t)(n0 + row) * K + ka;
            CP16(s + so,              Ah + ga);
            CP16(s + TILE_B + so,     Al + ga);
            CP16(s + 2 * TILE_B + so, Bh + gb);
            CP16(s + 3 * TILE_B + so, Bl + gb);
        }
    };

    load_stage(0, 0); CP_COMMIT();
    load_stage(1, 1); CP_COMMIT();

    // fragment relative offsets (stage-base-independent)
    const int a_r  = wm * 32 + (lane & 15);
    const int a_c0 = lane >> 4;                         // chunk bit (0/1)
    const int b_r  = wn * 64 + (lane & 7) + ((lane >> 4) << 3);
    const int b_c0 = (lane >> 3) & 1;

    for (int kt = 0; kt < NK; ++kt) {
        if (kt + 1 < NK) { CP_WAIT(1); } else { CP_WAIT(0); }
        __syncthreads();
        if (kt + 2 < NK) {
            load_stage((kt + 2) % NSTAGE, kt + 2);
            CP_COMMIT();
        }

        const uint32_t s = sbase + (kt % NSTAGE) * STG_B;
        #pragma unroll
        for (int ks = 0; ks < 2; ++ks) {
            uint32_t ah[2][4], al[2][4];
            #pragma unroll
            for (int mt = 0; mt < 2; ++mt) {
                uint32_t ro = SWZ2((uint32_t)((a_r + mt * 16) * 64 + (2 * ks + a_c0) * 16));
                LDM4(ah[mt], s + ro);
                LDM4(al[mt], s + TILE_B + ro);
            }
            #pragma unroll
            for (int np = 0; np < 4; ++np) {
                uint32_t ro = SWZ2((uint32_t)((b_r + np * 16) * 64 + (2 * ks + b_c0) * 16));
                uint32_t bh[4], bl[4];
                LDM4(bh, s + 2 * TILE_B + ro);
                LDM4(bl, s + 3 * TILE_B + ro);
                // 12 MMAs, accumulator reuse distance = 4
                MMA16816(acc[0][2 * np],     ah[0], bh[0], bh[1]);
                MMA16816(acc[1][2 * np],     ah[1], bh[0], bh[1]);
                MMA16816(acc[0][2 * np + 1], ah[0], bh[2], bh[3]);
                MMA16816(acc[1][2 * np + 1], ah[1], bh[2], bh[3]);
                MMA16816(acc[0][2 * np],     ah[0], bl[0], bl[1]);
                MMA16816(acc[1][2 * np],     ah[1], bl[0], bl[1]);
                MMA16816(acc[0][2 * np + 1], ah[0], bl[2], bl[3]);
                MMA16816(acc[1][2 * np + 1], ah[1], bl[2], bl[3]);
                MMA16816(acc[0][2 * np],     al[0], bh[0], bh[1]);
                MMA16816(acc[1][2 * np],     al[1], bh[0], bh[1]);
                MMA16816(acc[0][2 * np + 1], al[0], bh[2], bh[3]);
                MMA16816(acc[1][2 * np + 1], al[1], bh[2], bh[3]);
            }
        }
    }

    #pragma unroll
    for (int mt = 0; mt < 2; ++mt) {
        #pragma unroll
        for (int nt = 0; nt < 8; ++nt) {
            int row = m0 + wm * 32 + mt * 16 + (lane >> 2);
            int col = n0 + wn * 64 + nt * 8 + (lane & 3) * 2;
            float2 v0 = make_float2(acc[mt][nt][0], acc[mt][nt][1]);
            float2 v1 = make_float2(acc[mt][nt][2], acc[mt][nt][3]);
            *reinterpret_cast<float2*>(&C[(size_t)row * N + col]) = v0;
            *reinterpret_cast<float2*>(&C[(size_t)(row + 8) * N + col]) = v1;
        }
    }
}

// ---------------------------------------------------------------------------
// Tensor-core sliding-window attention (bf16x3, mma.sync) — as Round 5.
// ---------------------------------------------------------------------------
#define AST 72

__global__ __launch_bounds__(128, 4)
void attn_tc_kernel(const float* __restrict__ qkv,
                    __nv_bfloat16* __restrict__ out_hi,
                    __nv_bfloat16* __restrict__ out_lo) {
    extern __shared__ __nv_bfloat16 smb[];
    const int REG = 64 * AST;
    __nv_bfloat16* Qh = smb;
    __nv_bfloat16* Ql = smb + REG;
    __nv_bfloat16* Kh = smb + 2 * REG;
    __nv_bfloat16* Kl = smb + 3 * REG;
    __nv_bfloat16* Vh = smb + 4 * REG;
    __nv_bfloat16* Vl = smb + 5 * REG;

    const int tid  = threadIdx.x;
    const int lane = tid & 31;
    const int warp = tid >> 5;
    const int q0 = blockIdx.x * 64;
    const int h  = blockIdx.y;
    const int b  = blockIdx.z;
    const size_t base = (size_t)b * T_SEQ * N_QKV;
    const int hoff = h * DH;

    const uint32_t sQh = smem_u32(Qh), sQl = smem_u32(Ql);
    const uint32_t sKh = smem_u32(Kh), sKl = smem_u32(Kl);
    const uint32_t sVh = smem_u32(Vh), sVl = smem_u32(Vl);

    #pragma unroll
    for (int it = 0; it < 8; it++) {
        int idx = it * 128 + tid;
        int r = idx >> 4, d4 = (idx & 15) << 2;
        float4 f = *reinterpret_cast<const float4*>(
            &qkv[base + (size_t)(q0 + r) * N_QKV + hoff + d4]);
        split_store4(f, &Qh[r * AST + d4], &Ql[r * AST + d4]);
    }

    float sa[8][4];
    float o[8][4];
    #pragma unroll
    for (int t = 0; t < 8; t++)
        #pragma unroll
        for (int j = 0; j < 4; j++) o[t][j] = 0.f;
    float m0 = -1e20f, m1 = -1e20f, l0 = 0.f, l1 = 0.f;

    const int lane2 = (lane & 3) * 2;
    const int qrow  = warp * 16 + (lane >> 2);
    const int qg0   = q0 + qrow;

    const uint32_t a_off = (uint32_t)((warp * 16 + (lane & 15)) * AST + ((lane >> 4) << 3)) * 2;
    const uint32_t b_off = (uint32_t)(((lane & 7) + ((lane >> 4) << 3)) * AST + (((lane >> 3) & 1) << 3)) * 2;
    const uint32_t v_off = (uint32_t)((lane & 15) * AST + ((lane >> 4) << 3)) * 2;

    for (int c = 0; c < 5; c++) {
        const int kb = q0 - WIN + c * 64;
        __syncthreads();
        #pragma unroll
        for (int it = 0; it < 8; it++) {
            int idx = it * 128 + tid;
            int r = idx >> 4, d4 = (idx & 15) << 2;
            int kg = kb + r;
            float4 kf = make_float4(0.f, 0.f, 0.f, 0.f);
            float4 vf = kf;
            if (kg >= 0) {
                const float* p = &qkv[base + (size_t)kg * N_QKV + hoff + d4];
                kf = *reinterpret_cast<const float4*>(p + DM);
                vf = *reinterpret_cast<const float4*>(p + 2 * DM);
            }
            split_store4(kf, &Kh[r * AST + d4], &Kl[r * AST + d4]);
            split_store4(vf, &Vh[r * AST + d4], &Vl[r * AST + d4]);
        }
        __syncthreads();

        #pragma unroll
        for (int t = 0; t < 8; t++)
            #pragma unroll
            for (int j = 0; j < 4; j++) sa[t][j] = 0.f;

        #pragma unroll
        for (int ks = 0; ks < 4; ks++) {
            uint32_t ah[4], al[4];
            LDM4(ah, sQh + a_off + ks * 32);
            LDM4(al, sQl + a_off + ks * 32);
            #pragma unroll
            for (int np = 0; np < 4; np++) {
                uint32_t bh[4], bl[4];
                uint32_t ko = b_off + (uint32_t)(np * 16 * AST) * 2 + ks * 32;
                LDM4(bh, sKh + ko);
                LDM4(bl, sKl + ko);
                MMA16816(sa[2 * np],     ah, bh[0], bh[1]);
                MMA16816(sa[2 * np + 1], ah, bh[2], bh[3]);
                MMA16816(sa[2 * np],     ah, bl[0], bl[1]);
                MMA16816(sa[2 * np + 1], ah, bl[2], bl[3]);
                MMA16816(sa[2 * np],     al, bh[0], bh[1]);
                MMA16816(sa[2 * np + 1], al, bh[2], bh[3]);
            }
        }

        float mx0 = -1e30f, mx1 = -1e30f;
        #pragma unroll
        for (int t = 0; t < 8; t++) {
            #pragma unroll
            for (int j = 0; j < 4; j++) {
                int col = t * 8 + lane2 + (j & 1);
                int kg  = kb + col;
                int qg  = qg0 + ((j >> 1) << 3);
                bool valid = (kg >= 0) && (kg <= qg) && (kg >= qg - WIN);
                float s = valid ? sa[t][j] * 0.125f : -1e30f;
                sa[t][j] = s;
                if (j < 2) mx0 = fmaxf(mx0, s); else mx1 = fmaxf(mx1, s);
            }
        }
        mx0 = fmaxf(mx0, __shfl_xor_sync(0xffffffffu, mx0, 1));
        mx0 = fmaxf(mx0, __shfl_xor_sync(0xffffffffu, mx0, 2));
        mx1 = fmaxf(mx1, __shfl_xor_sync(0xffffffffu, mx1, 1));
        mx1 = fmaxf(mx1, __shfl_xor_sync(0xffffffffu, mx1, 2));

        const float mn0 = fmaxf(m0, mx0);
        const float mn1 = fmaxf(m1, mx1);
        const float sc0 = __expf(m0 - mn0);
        const float sc1 = __expf(m1 - mn1);
        m0 = mn0; m1 = mn1;

        float ps0 = 0.f, ps1 = 0.f;
        #pragma unroll
        for (int t = 0; t < 8; t++) {
            float p0 = __expf(sa[t][0] - mn0);
            float p1 = __expf(sa[t][1] - mn0);
            float p2 = __expf(sa[t][2] - mn1);
            float p3 = __expf(sa[t][3] - mn1);
            sa[t][0] = p0; sa[t][1] = p1; sa[t][2] = p2; sa[t][3] = p3;
            ps0 += p0 + p1; ps1 += p2 + p3;
        }
        ps0 += __shfl_xor_sync(0xffffffffu, ps0, 1);
        ps0 += __shfl_xor_sync(0xffffffffu, ps0, 2);
        ps1 += __shfl_xor_sync(0xffffffffu, ps1, 1);
        ps1 += __shfl_xor_sync(0xffffffffu, ps1, 2);
        l0 = l0 * sc0 + ps0;
        l1 = l1 * sc1 + ps1;

        #pragma unroll
        for (int t = 0; t < 8; t++) {
            o[t][0] *= sc0; o[t][1] *= sc0;
            o[t][2] *= sc1; o[t][3] *= sc1;
        }

        #pragma unroll
        for (int s = 0; s < 4; s++) {
            uint32_t aph[4], apl[4];
            pack2_hilo(sa[2 * s][0],     sa[2 * s][1],     aph[0], apl[0]);
            pack2_hilo(sa[2 * s][2],     sa[2 * s][3],     aph[1], apl[1]);
            pack2_hilo(sa[2 * s + 1][0], sa[2 * s + 1][1], aph[2], apl[2]);
            pack2_hilo(sa[2 * s + 1][2], sa[2 * s + 1][3], aph[3], apl[3]);
            #pragma unroll
            for (int nd = 0; nd < 4; nd++) {
                uint32_t vh[4], vl[4];
                uint32_t vo = v_off + (uint32_t)(s * 16 * AST) * 2 + nd * 32;
                LDM4T(vh, sVh + vo);
                LDM4T(vl, sVl + vo);
                MMA16816(o[2 * nd],     aph, vh[0], vh[1]);
                MMA16816(o[2 * nd + 1], aph, vh[2], vh[3]);
                MMA16816(o[2 * nd],     aph, vl[0], vl[1]);
                MMA16816(o[2 * nd + 1], aph, vl[2], vl[3]);
                MMA16816(o[2 * nd],     apl, vh[0], vh[1]);
                MMA16816(o[2 * nd + 1], apl, vh[2], vh[3]);
            }
        }
    }

    const float il0 = 1.f / l0;
    const float il1 = 1.f / l1;
    const size_t row0 = (size_t)(b * T_SEQ + qg0);
    #pragma unroll
    for (int t = 0; t < 8; t++) {
        int col = hoff + t * 8 + lane2;
        uint32_t h0, lo0, h1, lo1;
        pack2_hilo(o[t][0] * il0, o[t][1] * il0, h0, lo0);
        pack2_hilo(o[t][2] * il1, o[t][3] * il1, h1, lo1);
        *reinterpret_cast<uint32_t*>(&out_hi[row0 * DM + col])       = h0;
        *reinterpret_cast<uint32_t*>(&out_lo[row0 * DM + col])       = lo0;
        *reinterpret_cast<uint32_t*>(&out_hi[(row0 + 8) * DM + col]) = h1;
        *reinterpret_cast<uint32_t*>(&out_lo[(row0 + 8) * DM + col]) = lo1;
    }
}

// ---------------------------------------------------------------------------
extern "C" void kernel_launch(void* const* d_in, const int* in_sizes, int n_in,
                              void* d_out, int out_size) {
    const float* x     = (const float*)d_in[0];
    const float* w_qkv = (const float*)d_in[1];
    const float* w_out = (const float*)d_in[2];
    float* out = (float*)d_out;

    __nv_bfloat16 *x_hi, *x_lo, *wq_hi, *wq_lo, *wo_hi, *wo_lo, *at_hi, *at_lo;
    float *qkv_buf;
    cudaGetSymbolAddress((void**)&x_hi,  g_x_hi);
    cudaGetSymbolAddress((void**)&x_lo,  g_x_lo);
    cudaGetSymbolAddress((void**)&wq_hi, g_wqkvT_hi);
    cudaGetSymbolAddress((void**)&wq_lo, g_wqkvT_lo);
    cudaGetSymbolAddress((void**)&wo_hi, g_woutT_hi);
    cudaGetSymbolAddress((void**)&wo_lo, g_woutT_lo);
    cudaGetSymbolAddress((void**)&at_hi, g_att_hi);
    cudaGetSymbolAddress((void**)&at_lo, g_att_lo);
    cudaGetSymbolAddress((void**)&qkv_buf, g_qkv);

    cudaFuncSetAttribute(gemm_bf16x3, cudaFuncAttributeMaxDynamicSharedMemorySize, GEMM_SMEM);
    const int ATTN_SMEM = 6 * 64 * AST * (int)sizeof(__nv_bfloat16);        // 55296
    cudaFuncSetAttribute(attn_tc_kernel, cudaFuncAttributeMaxDynamicSharedMemorySize, ATTN_SMEM);

    // 0) precision splits / weight transposes
    {
        int n4 = M_ROWS * DM / 4;
        split_kernel<<<(n4 + 255) / 256, 256>>>(x, x_hi, x_lo, n4);
        dim3 g1(N_QKV / 32, DM / 32);
        transpose_split_kernel<<<g1, 256>>>(w_qkv, wq_hi, wq_lo, DM, N_QKV);
        dim3 g2(DM / 32, DM / 32);
        transpose_split_kernel<<<g2, 256>>>(w_out, wo_hi, wo_lo, DM, DM);
    }
    // 1) QKV projection
    {
        dim3 grid(N_QKV / BN, M_ROWS / BM);
        gemm_bf16x3<<<grid, 256, GEMM_SMEM>>>(x_hi, x_lo, wq_hi, wq_lo,
                                              qkv_buf, M_ROWS, N_QKV, DM);
    }
    // 2) attention
    {
        dim3 grid(T_SEQ / 64, NH, B_SZ);
        attn_tc_kernel<<<grid, 128, ATTN_SMEM>>>(qkv_buf, at_hi, at_lo);
    }
    // 3) output projection
    {
        dim3 grid(DM / BN, M_ROWS / BM);
        gemm_bf16x3<<<grid, 256, GEMM_SMEM>>>(at_hi, at_lo, wo_hi, wo_lo,
                                              out, M_ROWS, DM, DM);
    }
}